// round 9
// baseline (speedup 1.0000x reference)
#include <cuda_runtime.h>

// Problem constants
#define BQ   2
#define TT   1024
#define DD   1024
#define HH   16
#define DHD  64
#define KVL  3072
#define MEML 1024
#define CMEML 1024
#define SCALE_F 0.125f

// sigma(x) = ((x&3)<<1)|(x>>2)  -- interleave permutation within 8-groups
#define SIG(x) ((((x) & 3) << 1) | (((x) & 7) >> 2))

// ---------------- scratch (device globals; no allocation) ----------------
__device__ float g_kv_in [(long)BQ * KVL * DD];        // tf32 bits
__device__ float g_q     [(long)BQ * TT  * DD];        // tf32 bits, pre-scaled, d-permuted
__device__ float g_kv_out[(long)BQ * KVL * 2 * DD];    // tf32 bits; K half d-permuted
__device__ float g_ctx   [(long)BQ * TT  * DD];        // tf32 bits
__device__ float g_wt    [4096L * 1024];               // tf32 bits
__device__ float g_xtf   [(long)BQ * TT * DD];
__device__ float g_wqt   [1024L * 1024];
__device__ float g_wkvt  [1024L * 2048];
__device__ float g_woutt [1024L * 1024];
__device__ float g_memtf [(long)BQ * MEML * DD];
__device__ float g_ptf   [(long)HH * KVL * DHD];       // tf32 bits, d-permuted

// ---------------- TF32 + cp.async helpers --------------------------------
__device__ __forceinline__ unsigned f2tf(float f) {
    unsigned u;
    asm("cvt.rna.tf32.f32 %0, %1;" : "=r"(u) : "f"(f));
    return u;
}
__device__ __forceinline__ void mma_tf32(float c[4], const unsigned a[4], const unsigned b[2]) {
    asm volatile(
        "mma.sync.aligned.m16n8k8.row.col.f32.tf32.tf32.f32 "
        "{%0,%1,%2,%3},{%4,%5,%6,%7},{%8,%9},{%0,%1,%2,%3};"
        : "+f"(c[0]), "+f"(c[1]), "+f"(c[2]), "+f"(c[3])
        : "r"(a[0]), "r"(a[1]), "r"(a[2]), "r"(a[3]), "r"(b[0]), "r"(b[1]));
}
__device__ __forceinline__ void cp16(void* s, const void* g) {
    unsigned a = (unsigned)__cvta_generic_to_shared(s);
    asm volatile("cp.async.cg.shared.global [%0], [%1], 16;" :: "r"(a), "l"(g));
}
__device__ __forceinline__ void cp_commit() { asm volatile("cp.async.commit_group;"); }
template<int N> __device__ __forceinline__ void cp_wait() {
    asm volatile("cp.async.wait_group %0;" :: "n"(N));
}

// ---------------- convert fp32 -> tf32 bits ------------------------------
__global__ void cvt_kernel(const float4* __restrict__ src, float* __restrict__ dst, long n4) {
    long i = (long)blockIdx.x * blockDim.x + threadIdx.x;
    if (i >= n4) return;
    float4 v = src[i];
    uint4 t;
    t.x = f2tf(v.x); t.y = f2tf(v.y); t.z = f2tf(v.z); t.w = f2tf(v.w);
    *(uint4*)(dst + i * 4) = t;
}

// convert + d-permute (within 8-groups) for pos_emb
__global__ void cvt_perm_kernel(const float* __restrict__ src, float* __restrict__ dst, long n) {
    long i = (long)blockIdx.x * blockDim.x + threadIdx.x;
    if (i >= n) return;
    long d = i & 7;
    long p = (i & ~7L) | SIG(d);
    dst[p] = __uint_as_float(f2tf(src[i]));
}

// ---------------- kv concat: [cmem, mem, x] -> g_kv_in (tf32) -------------
__global__ void concat_kv_kernel(const float* __restrict__ x,
                                 const float* __restrict__ mem,
                                 const float* __restrict__ cmem) {
    long i4 = (long)blockIdx.x * blockDim.x + threadIdx.x;
    const long total4 = (long)BQ * KVL * DD / 4;
    if (i4 >= total4) return;
    long e = i4 * 4;
    int  b   = (int)(e / ((long)KVL * DD));
    long rem = e - (long)b * KVL * DD;
    int  t   = (int)(rem / DD);
    int  c   = (int)(rem - (long)t * DD);
    const float* src;
    if (t < CMEML)              src = cmem + (long)b * CMEML * DD + (long)t * DD + c;
    else if (t < CMEML + MEML)  src = mem  + (long)b * MEML  * DD + (long)(t - CMEML) * DD + c;
    else                        src = x    + (long)b * TT    * DD + (long)(t - CMEML - MEML) * DD + c;
    float4 v = *(const float4*)src;
    uint4 tv;
    tv.x = f2tf(v.x); tv.y = f2tf(v.y); tv.z = f2tf(v.z); tv.w = f2tf(v.w);
    *(uint4*)(g_kv_in + e) = tv;
}

// ---------------- async TF32 MMA GEMM (inputs pre-converted) --------------
// permN: output columns c < permN are written d-permuted (TF32OUT only).
template<int BM, int BN, int WM, int WN, bool TF32OUT>
__global__ __launch_bounds__(256) void mma_gemm_async(
    const float* __restrict__ A, const float* __restrict__ B,
    const float* __restrict__ bias, float* __restrict__ C,
    int K, int lda, int ldb, int ldc, float alpha, int permN, int ZH,
    long sAb, long sAh, long sBb, long sBh, long sCb, long sCh)
{
    int z = blockIdx.z;
    int zb = z / ZH, zh = z - zb * ZH;
    A += (long)zb * sAb + (long)zh * sAh;
    B += (long)zb * sBb + (long)zh * sBh;
    C += (long)zb * sCb + (long)zh * sCh;
    int m0 = blockIdx.y * BM, n0 = blockIdx.x * BN;

    __shared__ __align__(16) unsigned As[2][BM][20];
    __shared__ __align__(16) unsigned Bs[2][16][BN + 8];

    int tid  = threadIdx.x;
    int warp = tid >> 5, lane = tid & 31;
    int gid  = lane >> 2, tg = lane & 3;
    constexpr int WNN = BN / WN;
    int wm = warp / WNN, wn = warp % WNN;
    constexpr int MI = WM / 16, NI = WN / 8;

    float acc[MI][NI][4];
    #pragma unroll
    for (int mi = 0; mi < MI; mi++)
        #pragma unroll
        for (int ni = 0; ni < NI; ni++)
            #pragma unroll
            for (int u = 0; u < 4; u++) acc[mi][ni][u] = 0.f;

    auto issueTiles = [&](int k0, int buf) {
        #pragma unroll
        for (int i = 0; i < BM / 64; i++) {
            int f = tid + i * 256;
            int r = f >> 2, c = (f & 3) << 2;
            cp16(&As[buf][r][c], A + (long)(m0 + r) * lda + k0 + c);
        }
        constexpr int B4 = BN / 4;
        #pragma unroll
        for (int i = 0; i < BN / 64; i++) {
            int f = tid + i * 256;
            int r = f / B4, c = (f % B4) * 4;
            cp16(&Bs[buf][r][c], B + (long)(k0 + r) * ldb + n0 + c);
        }
        cp_commit();
    };

    issueTiles(0, 0);
    int nk = K / 16;
    for (int kt = 0; kt < nk; kt++) {
        int buf = kt & 1;
        if (kt + 1 < nk) {
            __syncthreads();
            issueTiles((kt + 1) * 16, buf ^ 1);
            cp_wait<1>();
        } else {
            cp_wait<0>();
        }
        __syncthreads();
        #pragma unroll
        for (int ks = 0; ks < 16; ks += 8) {
            unsigned af[MI][4], bf[NI][2];
            #pragma unroll
            for (int mi = 0; mi < MI; mi++) {
                int r = wm * WM + mi * 16;
                af[mi][0] = As[buf][r + gid][ks + tg];
                af[mi][1] = As[buf][r + gid + 8][ks + tg];
                af[mi][2] = As[buf][r + gid][ks + tg + 4];
                af[mi][3] = As[buf][r + gid + 8][ks + tg + 4];
            }
            #pragma unroll
            for (int ni = 0; ni < NI; ni++) {
                int cb = wn * WN + ni * 8;
                bf[ni][0] = Bs[buf][ks + tg][cb + gid];
                bf[ni][1] = Bs[buf][ks + tg + 4][cb + gid];
            }
            #pragma unroll
            for (int mi = 0; mi < MI; mi++)
                #pragma unroll
                for (int ni = 0; ni < NI; ni++)
                    mma_tf32(acc[mi][ni], af[mi], bf[ni]);
        }
    }

    #pragma unroll
    for (int mi = 0; mi < MI; mi++) {
        #pragma unroll
        for (int ni = 0; ni < NI; ni++) {
            int r0 = m0 + wm * WM + mi * 16 + gid;
            int c  = n0 + wn * WN + ni * 8 + 2 * tg;
            if (TF32OUT) {
                unsigned t0 = f2tf(alpha * acc[mi][ni][0]), t1 = f2tf(alpha * acc[mi][ni][1]);
                unsigned t2 = f2tf(alpha * acc[mi][ni][2]), t3 = f2tf(alpha * acc[mi][ni][3]);
                if (c < permN) {
                    int base = c & ~7;
                    int p0 = base | SIG(c & 7);
                    int p1 = base | SIG((c + 1) & 7);
                    float* row0 = C + (long)r0 * ldc;
                    float* row1 = C + (long)(r0 + 8) * ldc;
                    row0[p0] = __uint_as_float(t0); row0[p1] = __uint_as_float(t1);
                    row1[p0] = __uint_as_float(t2); row1[p1] = __uint_as_float(t3);
                } else {
                    *(uint2*)(C + (long)r0 * ldc + c)       = make_uint2(t0, t1);
                    *(uint2*)(C + (long)(r0 + 8) * ldc + c) = make_uint2(t2, t3);
                }
            } else {
                float b0 = 0.f, b1 = 0.f;
                if (bias) { b0 = bias[c]; b1 = bias[c + 1]; }
                float2 v0 = make_float2(alpha * acc[mi][ni][0] + b0, alpha * acc[mi][ni][1] + b1);
                float2 v1 = make_float2(alpha * acc[mi][ni][2] + b0, alpha * acc[mi][ni][3] + b1);
                *(float2*)(C + (long)r0 * ldc + c)       = v0;
                *(float2*)(C + (long)(r0 + 8) * ldc + c) = v1;
            }
        }
    }
}

// ---------------- fused flash attention (round-6 structure + LDS.64 frags) --
// 8 warps, i-tile 128, j-tile 64, grid (1,8,32). Q/K/pos d-permuted by SIG.
// smem: Ks[2][64][68] @0 (34816) | Vs[2][64][72] @34816 (36864)
//       Ps[2][192][68] @71680 (104448) | Pg[128][84] @176128 (43008) = 219136
#define FL_SMEM 219136

__global__ __launch_bounds__(256, 1) void flash_kernel(const float* __restrict__ pos_tf) {
    extern __shared__ __align__(16) unsigned char sm[];
    unsigned (*Ks)[64][68]  = (unsigned(*)[64][68]) (sm);
    unsigned (*Vs)[64][72]  = (unsigned(*)[64][72]) (sm + 34816);
    unsigned (*Ps)[192][68] = (unsigned(*)[192][68])(sm + 71680);
    float    (*Pg)[84]      = (float(*)[84])        (sm + 176128);

    int bh = blockIdx.z; int b = bh >> 4, h = bh & 15;
    int i0 = blockIdx.y << 7;
    int tid = threadIdx.x, warp = tid >> 5, lane = tid & 31;
    int gid = lane >> 2, tg = lane & 3;

    // Q fragments in registers (g_q pre-scaled, tf32, d-permuted: pair adjacent)
    unsigned qf[8][4];
    {
        const float* q0 = g_q + (long)(b * TT + i0 + (warp << 4) + gid) * DD + h * DHD;
        const float* q1 = q0 + 8 * DD;
        #pragma unroll
        for (int kb = 0; kb < 8; kb++) {
            uint2 a0 = *(const uint2*)(q0 + kb * 8 + 2 * tg);
            uint2 a1 = *(const uint2*)(q1 + kb * 8 + 2 * tg);
            qf[kb][0] = a0.x; qf[kb][2] = a0.y;
            qf[kb][1] = a1.x; qf[kb][3] = a1.y;
        }
    }

    int r = tid >> 2, cw = (tid & 3) << 4;
    int vrow = (r & 56) | SIG(r & 7);          // sigma-permuted V smem row
    const float* kvbase = g_kv_out + ((long)(b * KVL) + r) * (2 * DD) + h * DHD + cw;
    int ubase0 = 896 - i0;

    auto issue = [&](int j0, int buf) {
        const float* kp = kvbase + (long)j0 * (2 * DD);
        #pragma unroll
        for (int u = 0; u < 4; u++) cp16(&Ks[buf][r][cw + 4 * u], kp + 4 * u);
        const float* vp = kp + DD;
        #pragma unroll
        for (int u = 0; u < 4; u++) cp16(&Vs[buf][vrow][cw + 4 * u], vp + 4 * u);
        int ub = j0 + ubase0;
        #pragma unroll
        for (int it = 0; it < 3; it++) {
            int rr = r + it * 64;
            int uu = ub + rr;
            if (uu < KVL) {
                const float* pp = pos_tf + ((long)h * KVL + uu) * DHD + cw;
                #pragma unroll
                for (int q = 0; q < 4; q++) cp16(&Ps[buf][rr][cw + 4 * q], pp + 4 * q);
            } else {
                uint4 z = make_uint4(0, 0, 0, 0);
                #pragma unroll
                for (int q = 0; q < 4; q++) *(uint4*)&Ps[buf][rr][cw + 4 * q] = z;
            }
        }
        cp_commit();
    };

    float oacc[8][4] = {};
    float m0r = -1e30f, m1r = -1e30f, l0r = 0.f, l1r = 0.f;
    int wb = 112 - (warp << 4);
    int pgr0 = (warp << 4) + gid, pgr1 = pgr0 + 8;
    // prob-store columns (sigma of 2tg, 2tg+1)
    int pc0 = SIG(2 * tg), pc1 = SIG(2 * tg + 1);

    issue(0, 0);
    for (int t = 0; t < 48; t++) {
        int buf = t & 1;
        if (t < 47) {
            __syncthreads();
            issue((t + 1) << 6, buf ^ 1);
            cp_wait<1>();
        } else {
            cp_wait<0>();
        }
        __syncthreads();

        // ---- S = QK^T and band product (LDS.64 B-fragments) ----
        float sacc[8][4] = {}, pacc[10][4] = {};
        #pragma unroll
        for (int kb = 0; kb < 8; kb++) {
            #pragma unroll
            for (int nb = 0; nb < 8; nb++) {
                uint2 kk = *(const uint2*)&Ks[buf][nb * 8 + gid][kb * 8 + 2 * tg];
                unsigned bf[2] = { kk.x, kk.y };
                mma_tf32(sacc[nb], qf[kb], bf);
            }
            #pragma unroll
            for (int nb = 0; nb < 10; nb++) {
                uint2 pk = *(const uint2*)&Ps[buf][wb + nb * 8 + gid][kb * 8 + 2 * tg];
                unsigned bf[2] = { pk.x, pk.y };
                mma_tf32(pacc[nb], qf[kb], bf);
            }
        }

        // ---- dump band product, gather shifted into S (band-row dim, unpermuted) ----
        #pragma unroll
        for (int nb = 0; nb < 10; nb++) {
            Pg[pgr0][nb * 8 + 2 * tg]     = pacc[nb][0];
            Pg[pgr0][nb * 8 + 2 * tg + 1] = pacc[nb][1];
            Pg[pgr1][nb * 8 + 2 * tg]     = pacc[nb][2];
            Pg[pgr1][nb * 8 + 2 * tg + 1] = pacc[nb][3];
        }
        __syncwarp();
        {
            int s0 = 15 - gid, s1 = 7 - gid;
            #pragma unroll
            for (int nb = 0; nb < 8; nb++) {
                int jl = nb * 8 + 2 * tg;
                sacc[nb][0] += Pg[pgr0][jl + s0];
                sacc[nb][1] += Pg[pgr0][jl + 1 + s0];
                sacc[nb][2] += Pg[pgr1][jl + s1];
                sacc[nb][3] += Pg[pgr1][jl + 1 + s1];
            }
        }

        // ---- online softmax (rows quad-local) ----
        float mx0 = -1e30f, mx1 = -1e30f;
        #pragma unroll
        for (int nb = 0; nb < 8; nb++) {
            mx0 = fmaxf(mx0, fmaxf(sacc[nb][0], sacc[nb][1]));
            mx1 = fmaxf(mx1, fmaxf(sacc[nb][2], sacc[nb][3]));
        }
        #pragma unroll
        for (int o = 1; o <= 2; o <<= 1) {
            mx0 = fmaxf(mx0, __shfl_xor_sync(0xffffffffu, mx0, o));
            mx1 = fmaxf(mx1, __shfl_xor_sync(0xffffffffu, mx1, o));
        }
        float mn0 = fmaxf(m0r, mx0), mn1 = fmaxf(m1r, mx1);
        float f0 = __expf(m0r - mn0), f1 = __expf(m1r - mn1);
        m0r = mn0; m1r = mn1;
        float ps0 = 0.f, ps1 = 0.f;
        #pragma unroll
        for (int nb = 0; nb < 8; nb++) {
            sacc[nb][0] = __expf(sacc[nb][0] - mn0);
            sacc[nb][1] = __expf(sacc[nb][1] - mn0);
            sacc[nb][2] = __expf(sacc[nb][2] - mn1);
            sacc[nb][3] = __expf(sacc[nb][3] - mn1);
            ps0 += sacc[nb][0] + sacc[nb][1];
            ps1 += sacc[nb][2] + sacc[nb][3];
            oacc[nb][0] *= f0; oacc[nb][1] *= f0;
            oacc[nb][2] *= f1; oacc[nb][3] *= f1;
        }
        #pragma unroll
        for (int o = 1; o <= 2; o <<= 1) {
            ps0 += __shfl_xor_sync(0xffffffffu, ps0, o);
            ps1 += __shfl_xor_sync(0xffffffffu, ps1, o);
        }
        l0r = l0r * f0 + ps0;
        l1r = l1r * f1 + ps1;

        // ---- probs -> Pg with sigma on j (tf32) ----
        __syncwarp();
        #pragma unroll
        for (int nb = 0; nb < 8; nb++) {
            Pg[pgr0][nb * 8 + pc0] = __uint_as_float(f2tf(sacc[nb][0]));
            Pg[pgr0][nb * 8 + pc1] = __uint_as_float(f2tf(sacc[nb][1]));
            Pg[pgr1][nb * 8 + pc0] = __uint_as_float(f2tf(sacc[nb][2]));
            Pg[pgr1][nb * 8 + pc1] = __uint_as_float(f2tf(sacc[nb][3]));
        }
        __syncwarp();

        // ---- AV: A-frags via LDS.64, V rows sigma-permuted ----
        #pragma unroll
        for (int kb = 0; kb < 8; kb++) {
            float2 p0 = *(const float2*)&Pg[pgr0][kb * 8 + 2 * tg];
            float2 p1 = *(const float2*)&Pg[pgr1][kb * 8 + 2 * tg];
            unsigned af[4] = { __float_as_uint(p0.x), __float_as_uint(p1.x),
                               __float_as_uint(p0.y), __float_as_uint(p1.y) };
            #pragma unroll
            for (int nb = 0; nb < 8; nb++) {
                unsigned bf[2] = { Vs[buf][kb * 8 + 2 * tg][nb * 8 + gid],
                                   Vs[buf][kb * 8 + 2 * tg + 1][nb * 8 + gid] };
                mma_tf32(oacc[nb], af, bf);
            }
        }
    }

    // ---- write ctx = O / l as tf32 bits (d-dim of V: unpermuted) ----
    float inv0 = 1.0f / l0r, inv1 = 1.0f / l1r;
    #pragma unroll
    for (int nb = 0; nb < 8; nb++) {
        int c = h * DHD + nb * 8 + 2 * tg;
        long r0 = (long)(b * TT + i0 + (warp << 4) + gid) * DD + c;
        uint2 v0 = make_uint2(f2tf(oacc[nb][0] * inv0), f2tf(oacc[nb][1] * inv0));
        uint2 v1 = make_uint2(f2tf(oacc[nb][2] * inv1), f2tf(oacc[nb][3] * inv1));
        *(uint2*)(g_ctx + r0)          = v0;
        *(uint2*)(g_ctx + r0 + 8 * DD) = v1;
    }
}

// ---------------- conv weight transpose (tf32 out) ------------------------
__global__ void wtrans_kernel(const float* __restrict__ w) {
    long idx = (long)blockIdx.x * blockDim.x + threadIdx.x;
    if (idx >= 4096L * 1024) return;
    int k = (int)(idx >> 10);
    int o = (int)(idx & 1023);
    g_wt[idx] = __uint_as_float(f2tf(w[(long)o * 4096 + ((k & 1023) << 2) + (k >> 10)]));
}

// ---------------- simple vectorized copy + aux ---------------------------
__global__ void copy4_kernel(const float4* __restrict__ src, float4* __restrict__ dst, long n4) {
    long i = (long)blockIdx.x * blockDim.x + threadIdx.x;
    if (i < n4) dst[i] = src[i];
}
__global__ void aux_kernel(float* out) { *out = 0.f; }

// ---------------- launch ---------------------------------------------------
extern "C" void kernel_launch(void* const* d_in, const int* in_sizes, int n_in,
                              void* d_out_, int out_size) {
    const float* x      = (const float*)d_in[0];
    const float* mem    = (const float*)d_in[1];
    const float* cmem   = (const float*)d_in[2];
    const float* pos    = (const float*)d_in[3];
    const float* Wq     = (const float*)d_in[4];
    const float* Wkv    = (const float*)d_in[5];
    const float* Wout   = (const float*)d_in[6];
    const float* b_out  = (const float*)d_in[7];
    const float* conv_w = (const float*)d_in[8];
    const float* conv_b = (const float*)d_in[9];
    float* out = (float*)d_out_;

    float *p_kvin, *p_q, *p_kvout, *p_ctx, *p_wt;
    float *p_xtf, *p_wqt, *p_wkvt, *p_woutt, *p_memtf, *p_ptf;
    cudaGetSymbolAddress((void**)&p_kvin,  g_kv_in);
    cudaGetSymbolAddress((void**)&p_q,     g_q);
    cudaGetSymbolAddress((void**)&p_kvout, g_kv_out);
    cudaGetSymbolAddress((void**)&p_ctx,   g_ctx);
    cudaGetSymbolAddress((void**)&p_wt,    g_wt);
    cudaGetSymbolAddress((void**)&p_xtf,   g_xtf);
    cudaGetSymbolAddress((void**)&p_wqt,   g_wqt);
    cudaGetSymbolAddress((void**)&p_wkvt,  g_wkvt);
    cudaGetSymbolAddress((void**)&p_woutt, g_woutt);
    cudaGetSymbolAddress((void**)&p_memtf, g_memtf);
    cudaGetSymbolAddress((void**)&p_ptf,   g_ptf);

    cudaFuncSetAttribute(flash_kernel, cudaFuncAttributeMaxDynamicSharedMemorySize, FL_SMEM);

    // pre-convert operands to tf32 bits (pos also d-permuted)
    concat_kv_kernel<<<6144, 256>>>(x, mem, cmem);
    cvt_kernel<<<2048, 256>>>((const float4*)x,    p_xtf,   524288);
    cvt_kernel<<<1024, 256>>>((const float4*)Wq,   p_wqt,   262144);
    cvt_kernel<<<2048, 256>>>((const float4*)Wkv,  p_wkvt,  524288);
    cvt_kernel<<<1024, 256>>>((const float4*)Wout, p_woutt, 262144);
    cvt_kernel<<<2048, 256>>>((const float4*)mem,  p_memtf, 524288);
    cvt_perm_kernel<<<12288, 256>>>(pos, p_ptf, 3145728);
    wtrans_kernel<<<16384, 256>>>(conv_w);

    // q = SCALE * x @ Wq  (tf32 out, pre-scaled, d-permuted)
    mma_gemm_async<128,128,64,32,true><<<dim3(8, 16, 1), 256>>>(
        p_xtf, p_wqt, nullptr, p_q, 1024, 1024, 1024, 1024, SCALE_F, 1024, 1, 0,0, 0,0, 0,0);
    // kv = kv_in @ Wkv  (tf32 out, K half (cols<1024) d-permuted, V half plain)
    mma_gemm_async<128,128,64,32,true><<<dim3(16, 48, 1), 256>>>(
        p_kvin, p_wkvt, nullptr, p_kvout, 1024, 1024, 2048, 2048, 1.0f, 1024, 1, 0,0, 0,0, 0,0);

    // fused attention (8 warps, i-tile 128)
    flash_kernel<<<dim3(1, 8, 32), 256, FL_SMEM>>>(p_ptf);

    // logits = ctx @ Wout + b_out
    mma_gemm_async<128,128,64,32,false><<<dim3(8, 16, 1), 256>>>(
        p_ctx, p_woutt, b_out, out, 1024, 1024, 1024, 1024, 1.0f, 0, 1, 0,0, 0,0, 0,0);

    // new_mem = x
    copy4_kernel<<<2048, 256>>>((const float4*)x, (float4*)(out + 2097152), 524288);

    // new_cmem part 1: cmem[:, 256:]
    copy4_kernel<<<768, 256>>>((const float4*)(cmem + 262144),  (float4*)(out + 4194304), 196608);
    copy4_kernel<<<768, 256>>>((const float4*)(cmem + 1310720), (float4*)(out + 5242880), 196608);

    // new_cmem part 2: conv as GEMM (M=256, K=4096, N=1024) per batch
    mma_gemm_async<128,128,64,32,false><<<dim3(8, 2, 2), 256>>>(
        p_memtf, p_wt, conv_b, out + 4980736, 4096, 4096, 1024, 1024, 1.0f, 0, 1,
        1048576L, 0L, 0L, 0L, 1048576L, 0L);

    // aux_loss = 0
    aux_kernel<<<1, 1>>>(out + 6291456);
}

// round 10
// speedup vs baseline: 2.2293x; 2.2293x over previous
#include <cuda_runtime.h>
#include <cuda_fp16.h>

// Problem constants
#define BQ   2
#define TT   1024
#define DD   1024
#define HH   16
#define DHD  64
#define KVL  3072
#define MEML 1024
#define SCALE_F 0.125f

// ---------------- scratch (device globals; no allocation) ----------------
__device__ __half g_xh   [2048L * 1024];
__device__ __half g_memh [2048L * 1024];
__device__ __half g_ph   [16L * 3072 * 64];
__device__ __half g_kvinh[6144L * 1024];
__device__ __half g_qh   [2048L * 1024];     // pre-scaled by SCALE
__device__ __half g_kvh  [6144L * 2048];     // K cols 0..1023, V cols 1024..2047
__device__ __half g_ctxh [2048L * 1024];
__device__ __half g_wqth [1024L * 1024];     // Wq^T
__device__ __half g_wkvth[2048L * 1024];     // Wkv^T
__device__ __half g_wouth[1024L * 1024];     // Wout^T
__device__ __half g_wtth [1024L * 4096];     // conv weight [o][k]

// ---------------- helpers ------------------------------------------------
__device__ __forceinline__ void mma_f16(float c[4], const unsigned a[4],
                                        unsigned b0, unsigned b1) {
    asm volatile(
        "mma.sync.aligned.m16n8k16.row.col.f32.f16.f16.f32 "
        "{%0,%1,%2,%3},{%4,%5,%6,%7},{%8,%9},{%0,%1,%2,%3};"
        : "+f"(c[0]), "+f"(c[1]), "+f"(c[2]), "+f"(c[3])
        : "r"(a[0]), "r"(a[1]), "r"(a[2]), "r"(a[3]), "r"(b0), "r"(b1));
}
__device__ __forceinline__ void ldsm4t(unsigned& r0, unsigned& r1,
                                       unsigned& r2, unsigned& r3, unsigned addr) {
    asm volatile("ldmatrix.sync.aligned.m8n8.x4.trans.shared.b16 {%0,%1,%2,%3}, [%4];"
        : "=r"(r0), "=r"(r1), "=r"(r2), "=r"(r3) : "r"(addr));
}
__device__ __forceinline__ void cp16(void* s, const void* g) {
    unsigned a = (unsigned)__cvta_generic_to_shared(s);
    asm volatile("cp.async.cg.shared.global [%0], [%1], 16;" :: "r"(a), "l"(g));
}
__device__ __forceinline__ void cp_commit() { asm volatile("cp.async.commit_group;"); }
template<int N> __device__ __forceinline__ void cp_wait() {
    asm volatile("cp.async.wait_group %0;" :: "n"(N));
}
__device__ __forceinline__ unsigned packh2(float lo, float hi) {
    __half2 h = __floats2half2_rn(lo, hi);
    return *(unsigned*)&h;
}

// ---------------- convert f32 -> half (8 elems/thread) -------------------
__global__ void cvt_h_kernel(const float4* __restrict__ src, __half* __restrict__ dst, long n8) {
    long i = (long)blockIdx.x * blockDim.x + threadIdx.x;
    if (i >= n8) return;
    float4 a = src[i * 2], b = src[i * 2 + 1];
    uint4 o;
    o.x = packh2(a.x, a.y); o.y = packh2(a.z, a.w);
    o.z = packh2(b.x, b.y); o.w = packh2(b.z, b.w);
    *(uint4*)(dst + i * 8) = o;
}

// ---------------- kv concat: [cmem, mem, x] -> g_kvinh (half) ------------
__global__ void concat_h_kernel(const float* __restrict__ x,
                                const float* __restrict__ mem,
                                const float* __restrict__ cmem) {
    long i8 = (long)blockIdx.x * blockDim.x + threadIdx.x;
    if (i8 >= 786432L) return;
    long e = i8 * 8;
    int  b   = (int)(e / (3072L * 1024));
    long rem = e - (long)b * 3072 * 1024;
    int  t   = (int)(rem / 1024);
    int  c   = (int)(rem - (long)t * 1024);
    const float* src;
    if (t < 1024)       src = cmem + (long)b * 1048576 + (long)t * 1024 + c;
    else if (t < 2048)  src = mem  + (long)b * 1048576 + (long)(t - 1024) * 1024 + c;
    else                src = x    + (long)b * 1048576 + (long)(t - 2048) * 1024 + c;
    float4 a = *(const float4*)src, d = *(const float4*)(src + 4);
    uint4 o;
    o.x = packh2(a.x, a.y); o.y = packh2(a.z, a.w);
    o.z = packh2(d.x, d.y); o.w = packh2(d.z, d.w);
    *(uint4*)(g_kvinh + e) = o;
}

// ---------------- transpose + convert: in[R][C] -> out[C][R] half --------
__global__ void thalf_kernel(const float* __restrict__ in, __half* __restrict__ out,
                             int R, int C) {
    __shared__ float t[32][33];
    int bx = blockIdx.x << 5, by = blockIdx.y << 5;
    int tx = threadIdx.x & 31, ty = threadIdx.x >> 5;
    #pragma unroll
    for (int i = 0; i < 4; i++)
        t[ty + i * 8][tx] = in[(long)(by + ty + i * 8) * C + bx + tx];
    __syncthreads();
    #pragma unroll
    for (int i = 0; i < 4; i++)
        out[(long)(bx + ty + i * 8) * R + by + tx] = __float2half_rn(t[tx][ty + i * 8]);
}

// ---------------- conv weight gather: (O,I,4) -> [o][k=r*1024+i] half ----
__global__ void wtt_kernel(const float* __restrict__ w) {
    long idx = (long)blockIdx.x * blockDim.x + threadIdx.x;
    if (idx >= 4194304L) return;
    int o = (int)(idx >> 12), k = (int)(idx & 4095);
    g_wtth[idx] = __float2half_rn(w[((long)o << 12) + ((k & 1023) << 2) + (k >> 10)]);
}

// ---------------- f16 MMA GEMM: C = alpha*A @ Bt^T (+bias) ---------------
// A: MxK half row-major. Bt: NxK half (pre-transposed B). 256 thr, BM=BN=128.
// OUTH=1: write half (alpha applied). OUTH=0: write f32 + bias.
template<int OUTH>
__global__ __launch_bounds__(256) void hgemm(
    const __half* __restrict__ A, const __half* __restrict__ Bt,
    const float* __restrict__ bias, void* __restrict__ Cv,
    int K, int lda, int ldb, int ldc, float alpha, long sA, long sC)
{
    extern __shared__ __half hsm[];
    __half (*As)[56] = (__half(*)[56])hsm;                 // [2*128][56]
    __half (*Bs)[56] = (__half(*)[56])(hsm + 2 * 128 * 56);

    int z = blockIdx.z;
    A += (long)z * sA;
    int m0 = blockIdx.y << 7, n0 = blockIdx.x << 7;

    int tid = threadIdx.x, warp = tid >> 5, lane = tid & 31;
    int gid = lane >> 2, tg = lane & 3;
    int wm = warp >> 2, wn = warp & 3;   // WM=64, WN=32

    float acc[4][4][4] = {};

    auto issueT = [&](int k0, int buf) {
        #pragma unroll
        for (int i = 0; i < 2; i++) {
            int f = tid + i * 256;
            int r = f >> 2, c = (f & 3) << 3;
            cp16(&As[buf * 128 + r][c], A + (long)(m0 + r) * lda + k0 + c);
            cp16(&Bs[buf * 128 + r][c], Bt + (long)(n0 + r) * ldb + k0 + c);
        }
        cp_commit();
    };

    issueT(0, 0);
    int nk = K >> 5;
    for (int kt = 0; kt < nk; kt++) {
        int buf = kt & 1;
        if (kt + 1 < nk) {
            __syncthreads();
            issueT((kt + 1) << 5, buf ^ 1);
            cp_wait<1>();
        } else {
            cp_wait<0>();
        }
        __syncthreads();
        #pragma unroll
        for (int ks = 0; ks < 32; ks += 16) {
            unsigned af[4][4], bf[4][2];
            #pragma unroll
            for (int mi = 0; mi < 4; mi++) {
                const __half* ar = &As[buf * 128 + wm * 64 + mi * 16 + gid][ks + 2 * tg];
                af[mi][0] = *(const unsigned*)ar;
                af[mi][1] = *(const unsigned*)(ar + 8 * 56);
                af[mi][2] = *(const unsigned*)(ar + 8);
                af[mi][3] = *(const unsigned*)(ar + 8 * 56 + 8);
            }
            #pragma unroll
            for (int ni = 0; ni < 4; ni++) {
                const __half* br = &Bs[buf * 128 + wn * 32 + ni * 8 + gid][ks + 2 * tg];
                bf[ni][0] = *(const unsigned*)br;
                bf[ni][1] = *(const unsigned*)(br + 8);
            }
            #pragma unroll
            for (int mi = 0; mi < 4; mi++)
                #pragma unroll
                for (int ni = 0; ni < 4; ni++)
                    mma_f16(acc[mi][ni], af[mi], bf[ni][0], bf[ni][1]);
        }
    }

    #pragma unroll
    for (int mi = 0; mi < 4; mi++) {
        #pragma unroll
        for (int ni = 0; ni < 4; ni++) {
            int r0 = m0 + wm * 64 + mi * 16 + gid;
            int c  = n0 + wn * 32 + ni * 8 + 2 * tg;
            if (OUTH) {
                __half* C = (__half*)Cv + (long)z * sC;
                *(unsigned*)(C + (long)r0 * ldc + c) =
                    packh2(alpha * acc[mi][ni][0], alpha * acc[mi][ni][1]);
                *(unsigned*)(C + (long)(r0 + 8) * ldc + c) =
                    packh2(alpha * acc[mi][ni][2], alpha * acc[mi][ni][3]);
            } else {
                float* C = (float*)Cv + (long)z * sC;
                float b0 = 0.f, b1 = 0.f;
                if (bias) { b0 = bias[c]; b1 = bias[c + 1]; }
                *(float2*)(C + (long)r0 * ldc + c) =
                    make_float2(acc[mi][ni][0] + b0, acc[mi][ni][1] + b1);
                *(float2*)(C + (long)(r0 + 8) * ldc + c) =
                    make_float2(acc[mi][ni][2] + b0, acc[mi][ni][3] + b1);
            }
        }
    }
}

// ---------------- fused flash attention, fp16, 2 CTAs/SM ------------------
// 8 warps, i-tile 128, j-tile 64, grid (1,8,32).
// smem (107520 B): Ks[2][64][72]h @0 | Vs[2][64][72]h @18432
//                  Ps[192][72]h @36864 | Pg[128][84]f @64512
#define KS_OFF 0
#define VS_OFF 18432
#define PS_OFF 36864
#define PG_OFF 64512
#define FL_SMEM 107520

__global__ __launch_bounds__(256, 2) void flash_kernel() {
    extern __shared__ __align__(16) unsigned char sm[];
    __half (*Ks)[64][72] = (__half(*)[64][72])(sm + KS_OFF);
    __half (*Vs)[64][72] = (__half(*)[64][72])(sm + VS_OFF);
    __half (*Ps)[72]     = (__half(*)[72])(sm + PS_OFF);
    float  (*Pg)[84]     = (float(*)[84])(sm + PG_OFF);

    int bh = blockIdx.z; int b = bh >> 4, h = bh & 15;
    int i0 = blockIdx.y << 7;
    int tid = threadIdx.x, warp = tid >> 5, lane = tid & 31;
    int gid = lane >> 2, tg = lane & 3;

    // Q fragments (g_qh pre-scaled half)
    unsigned qf[4][4];
    {
        const __half* q0 = g_qh + (long)(b * TT + i0 + (warp << 4) + gid) * DD + h * DHD;
        #pragma unroll
        for (int kb = 0; kb < 4; kb++) {
            qf[kb][0] = *(const unsigned*)(q0 + kb * 16 + 2 * tg);
            qf[kb][1] = *(const unsigned*)(q0 + 8 * DD + kb * 16 + 2 * tg);
            qf[kb][2] = *(const unsigned*)(q0 + kb * 16 + 2 * tg + 8);
            qf[kb][3] = *(const unsigned*)(q0 + 8 * DD + kb * 16 + 2 * tg + 8);
        }
    }

    int r = tid >> 2, q4 = (tid & 3) << 4;
    const __half* kvb = g_kvh + ((long)(b * KVL) + r) * 2048 + h * DHD + q4;
    int ub0 = 896 - i0;

    auto issue = [&](int j0, int buf) {
        const __half* kp = kvb + (long)j0 * 2048;
        cp16(&Ks[buf][r][q4], kp);            cp16(&Ks[buf][r][q4 + 8], kp + 8);
        cp16(&Vs[buf][r][q4], kp + 1024);     cp16(&Vs[buf][r][q4 + 8], kp + 1032);
        int ub = j0 + ub0;
        #pragma unroll
        for (int it = 0; it < 3; it++) {
            int rr = r + it * 64;
            int uu = ub + rr;
            if (uu < KVL) {
                const __half* pp = g_ph + ((long)h * KVL + uu) * 64 + q4;
                cp16(&Ps[rr][q4], pp); cp16(&Ps[rr][q4 + 8], pp + 8);
            } else {
                uint4 z = make_uint4(0, 0, 0, 0);
                *(uint4*)&Ps[rr][q4] = z; *(uint4*)&Ps[rr][q4 + 8] = z;
            }
        }
        cp_commit();
    };

    // ldmatrix V addresses: lane -> (row, col) within 16x16 block
    int vrow = (lane & 7) + ((lane >> 3) & 1) * 8;
    int vcol = (lane >> 4) * 8;
    unsigned vbase = (unsigned)__cvta_generic_to_shared(&Vs[0][vrow][vcol]);

    float oacc[8][4] = {};
    float m0r = -1e30f, m1r = -1e30f, l0r = 0.f, l1r = 0.f;
    int wb = 112 - (warp << 4);
    int pgr0 = (warp << 4) + gid, pgr1 = pgr0 + 8;

    issue(0, 0);
    for (int t = 0; t < 48; t++) {
        int buf = t & 1;
        cp_wait<0>();
        __syncthreads();

        // ---- S = QK^T ----
        float sacc[8][4] = {};
        #pragma unroll
        for (int kb = 0; kb < 4; kb++)
            #pragma unroll
            for (int nb = 0; nb < 8; nb++) {
                const __half* kr = &Ks[buf][nb * 8 + gid][kb * 16 + 2 * tg];
                mma_f16(sacc[nb], qf[kb], *(const unsigned*)kr, *(const unsigned*)(kr + 8));
            }

        // ---- band product, 2 passes of 5 nb ----
        #pragma unroll
        for (int hp = 0; hp < 2; hp++) {
            float pacc[5][4] = {};
            #pragma unroll
            for (int kb = 0; kb < 4; kb++)
                #pragma unroll
                for (int nb = 0; nb < 5; nb++) {
                    const __half* pr = &Ps[wb + (hp * 5 + nb) * 8 + gid][kb * 16 + 2 * tg];
                    mma_f16(pacc[nb], qf[kb], *(const unsigned*)pr, *(const unsigned*)(pr + 8));
                }
            #pragma unroll
            for (int nb = 0; nb < 5; nb++) {
                int c = (hp * 5 + nb) * 8 + 2 * tg;
                Pg[pgr0][c] = pacc[nb][0]; Pg[pgr0][c + 1] = pacc[nb][1];
                Pg[pgr1][c] = pacc[nb][2]; Pg[pgr1][c + 1] = pacc[nb][3];
            }
        }
        __syncthreads();                     // Ks/Ps consumed, Pg dumped
        if (t < 47) issue((t + 1) << 6, buf ^ 1);

        // ---- gather shifted band into S ----
        {
            int s0 = 15 - gid, s1 = 7 - gid;
            #pragma unroll
            for (int nb = 0; nb < 8; nb++) {
                int jl = nb * 8 + 2 * tg;
                sacc[nb][0] += Pg[pgr0][jl + s0];
                sacc[nb][1] += Pg[pgr0][jl + 1 + s0];
                sacc[nb][2] += Pg[pgr1][jl + s1];
                sacc[nb][3] += Pg[pgr1][jl + 1 + s1];
            }
        }

        // ---- online softmax (rows quad-local) ----
        float mx0 = -1e30f, mx1 = -1e30f;
        #pragma unroll
        for (int nb = 0; nb < 8; nb++) {
            mx0 = fmaxf(mx0, fmaxf(sacc[nb][0], sacc[nb][1]));
            mx1 = fmaxf(mx1, fmaxf(sacc[nb][2], sacc[nb][3]));
        }
        #pragma unroll
        for (int o = 1; o <= 2; o <<= 1) {
            mx0 = fmaxf(mx0, __shfl_xor_sync(0xffffffffu, mx0, o));
            mx1 = fmaxf(mx1, __shfl_xor_sync(0xffffffffu, mx1, o));
        }
        float mn0 = fmaxf(m0r, mx0), mn1 = fmaxf(m1r, mx1);
        float f0 = __expf(m0r - mn0), f1 = __expf(m1r - mn1);
        m0r = mn0; m1r = mn1;
        float ps0 = 0.f, ps1 = 0.f;
        #pragma unroll
        for (int nb = 0; nb < 8; nb++) {
            sacc[nb][0] = __expf(sacc[nb][0] - mn0);
            sacc[nb][1] = __expf(sacc[nb][1] - mn0);
            sacc[nb][2] = __expf(sacc[nb][2] - mn1);
            sacc[nb][3] = __expf(sacc[nb][3] - mn1);
            ps0 += sacc[nb][0] + sacc[nb][1];
            ps1 += sacc[nb][2] + sacc[nb][3];
            oacc[nb][0] *= f0; oacc[nb][1] *= f0;
            oacc[nb][2] *= f1; oacc[nb][3] *= f1;
        }
        #pragma unroll
        for (int o = 1; o <= 2; o <<= 1) {
            ps0 += __shfl_xor_sync(0xffffffffu, ps0, o);
            ps1 += __shfl_xor_sync(0xffffffffu, ps1, o);
        }
        l0r = l0r * f0 + ps0;
        l1r = l1r * f1 + ps1;

        // ---- AV: probs -> in-register A-frags; V via ldmatrix.trans ----
        #pragma unroll
        for (int kb = 0; kb < 4; kb++) {
            unsigned af[4];
            af[0] = packh2(sacc[2 * kb][0],     sacc[2 * kb][1]);
            af[1] = packh2(sacc[2 * kb][2],     sacc[2 * kb][3]);
            af[2] = packh2(sacc[2 * kb + 1][0], sacc[2 * kb + 1][1]);
            af[3] = packh2(sacc[2 * kb + 1][2], sacc[2 * kb + 1][3]);
            unsigned va = vbase + buf * 9216 + kb * 2304;
            #pragma unroll
            for (int p = 0; p < 4; p++) {
                unsigned b0, b1, b2, b3;
                ldsm4t(b0, b1, b2, b3, va + p * 32);
                mma_f16(oacc[2 * p],     af, b0, b1);
                mma_f16(oacc[2 * p + 1], af, b2, b3);
            }
        }
    }

    // ---- write ctx = O / l as half ----
    float inv0 = 1.0f / l0r, inv1 = 1.0f / l1r;
    #pragma unroll
    for (int nb = 0; nb < 8; nb++) {
        int c = h * DHD + nb * 8 + 2 * tg;
        long r0 = (long)(b * TT + i0 + (warp << 4) + gid) * DD + c;
        *(unsigned*)(g_ctxh + r0)          = packh2(oacc[nb][0] * inv0, oacc[nb][1] * inv0);
        *(unsigned*)(g_ctxh + r0 + 8 * DD) = packh2(oacc[nb][2] * inv1, oacc[nb][3] * inv1);
    }
}

// ---------------- copies + aux -------------------------------------------
__global__ void copy4_kernel(const float4* __restrict__ src, float4* __restrict__ dst, long n4) {
    long i = (long)blockIdx.x * blockDim.x + threadIdx.x;
    if (i < n4) dst[i] = src[i];
}
__global__ void aux_kernel(float* out) { *out = 0.f; }

// ---------------- launch ---------------------------------------------------
extern "C" void kernel_launch(void* const* d_in, const int* in_sizes, int n_in,
                              void* d_out_, int out_size) {
    const float* x      = (const float*)d_in[0];
    const float* mem    = (const float*)d_in[1];
    const float* cmem   = (const float*)d_in[2];
    const float* pos    = (const float*)d_in[3];
    const float* Wq     = (const float*)d_in[4];
    const float* Wkv    = (const float*)d_in[5];
    const float* Wout   = (const float*)d_in[6];
    const float* b_out  = (const float*)d_in[7];
    const float* conv_w = (const float*)d_in[8];
    const float* conv_b = (const float*)d_in[9];
    float* out = (float*)d_out_;

    __half *p_xh, *p_memh, *p_ph, *p_kvinh, *p_qh, *p_kvh, *p_ctxh;
    __half *p_wqth, *p_wkvth, *p_wouth, *p_wtth;
    cudaGetSymbolAddress((void**)&p_xh,    g_xh);
    cudaGetSymbolAddress((void**)&p_memh,  g_memh);
    cudaGetSymbolAddress((void**)&p_ph,    g_ph);
    cudaGetSymbolAddress((void**)&p_kvinh, g_kvinh);
    cudaGetSymbolAddress((void**)&p_qh,    g_qh);
    cudaGetSymbolAddress((void**)&p_kvh,   g_kvh);
    cudaGetSymbolAddress((void**)&p_ctxh,  g_ctxh);
    cudaGetSymbolAddress((void**)&p_wqth,  g_wqth);
    cudaGetSymbolAddress((void**)&p_wkvth, g_wkvth);
    cudaGetSymbolAddress((void**)&p_wouth, g_wouth);
    cudaGetSymbolAddress((void**)&p_wtth,  g_wtth);

    cudaFuncSetAttribute(flash_kernel, cudaFuncAttributeMaxDynamicSharedMemorySize, FL_SMEM);
    cudaFuncSetAttribute(hgemm<0>, cudaFuncAttributeMaxDynamicSharedMemorySize, 57344);
    cudaFuncSetAttribute(hgemm<1>, cudaFuncAttributeMaxDynamicSharedMemorySize, 57344);

    // pre-convert to half
    concat_h_kernel<<<3072, 256>>>(x, mem, cmem);
    cvt_h_kernel<<<1024, 256>>>((const float4*)x,   p_xh,   262144);
    cvt_h_kernel<<<1024, 256>>>((const float4*)mem, p_memh, 262144);
    cvt_h_kernel<<<1536, 256>>>((const float4*)pos, p_ph,   393216);
    thalf_kernel<<<dim3(32, 32), 256>>>(Wq,   p_wqth,  1024, 1024);
    thalf_kernel<<<dim3(64, 32), 256>>>(Wkv,  p_wkvth, 1024, 2048);
    thalf_kernel<<<dim3(32, 32), 256>>>(Wout, p_wouth, 1024, 1024);
    wtt_kernel<<<16384, 256>>>(conv_w);

    // q = SCALE * x @ Wq  (half out, pre-scaled)
    hgemm<1><<<dim3(8, 16, 1), 256, 57344>>>(
        p_xh, p_wqth, nullptr, p_qh, 1024, 1024, 1024, 1024, SCALE_F, 0, 0);
    // kv = kv_in @ Wkv  (half out)
    hgemm<1><<<dim3(16, 48, 1), 256, 57344>>>(
        p_kvinh, p_wkvth, nullptr, p_kvh, 1024, 1024, 1024, 2048, 1.0f, 0, 0);

    // fused attention
    flash_kernel<<<dim3(1, 8, 32), 256, FL_SMEM>>>();

    // logits = ctx @ Wout + b_out (f32)
    hgemm<0><<<dim3(8, 16, 1), 256, 57344>>>(
        p_ctxh, p_wouth, b_out, out, 1024, 1024, 1024, 1024, 1.0f, 0, 0);

    // new_mem = x (f32 copy)
    copy4_kernel<<<2048, 256>>>((const float4*)x, (float4*)(out + 2097152), 524288);

    // new_cmem part 1: cmem[:, 256:]
    copy4_kernel<<<768, 256>>>((const float4*)(cmem + 262144),  (float4*)(out + 4194304), 196608);
    copy4_kernel<<<768, 256>>>((const float4*)(cmem + 1310720), (float4*)(out + 5242880), 196608);

    // new_cmem part 2: conv as GEMM (M=256, K=4096, N=1024) per batch
    hgemm<0><<<dim3(8, 2, 2), 256, 57344>>>(
        p_memh, p_wtth, conv_b, out + 4980736, 4096, 4096, 4096, 1024, 1.0f,
        1048576L, 1048576L);

    // aux_loss = 0
    aux_kernel<<<1, 1>>>(out + 6291456);
}

// round 11
// speedup vs baseline: 2.3106x; 1.0365x over previous
#include <cuda_runtime.h>
#include <cuda_fp16.h>

// Problem constants
#define BQ   2
#define TT   1024
#define DD   1024
#define HH   16
#define DHD  64
#define KVL  3072
#define MEML 1024
#define SCALE_F 0.125f

// ---------------- scratch (device globals; no allocation) ----------------
__device__ __half g_ph   [16L * 3072 * 64];
__device__ __half g_kvinh[6144L * 1024];     // [cmem|mem|x] per batch, half
__device__ __half g_qh   [2048L * 1024];     // pre-scaled by SCALE
__device__ __half g_kvh  [6144L * 2048];     // K cols 0..1023, V cols 1024..2047
__device__ __half g_ctxh [2048L * 1024];
__device__ __half g_wqth [1024L * 1024];     // Wq^T
__device__ __half g_wkvth[2048L * 1024];     // Wkv^T
__device__ __half g_wouth[1024L * 1024];     // Wout^T
__device__ __half g_wtth [1024L * 4096];     // conv weight [o][k]

// ---------------- helpers ------------------------------------------------
__device__ __forceinline__ void mma_f16(float c[4], const unsigned a[4],
                                        unsigned b0, unsigned b1) {
    asm volatile(
        "mma.sync.aligned.m16n8k16.row.col.f32.f16.f16.f32 "
        "{%0,%1,%2,%3},{%4,%5,%6,%7},{%8,%9},{%0,%1,%2,%3};"
        : "+f"(c[0]), "+f"(c[1]), "+f"(c[2]), "+f"(c[3])
        : "r"(a[0]), "r"(a[1]), "r"(a[2]), "r"(a[3]), "r"(b0), "r"(b1));
}
__device__ __forceinline__ void ldsm4(unsigned& r0, unsigned& r1,
                                      unsigned& r2, unsigned& r3, unsigned addr) {
    asm volatile("ldmatrix.sync.aligned.m8n8.x4.shared.b16 {%0,%1,%2,%3}, [%4];"
        : "=r"(r0), "=r"(r1), "=r"(r2), "=r"(r3) : "r"(addr));
}
__device__ __forceinline__ void ldsm4t(unsigned& r0, unsigned& r1,
                                       unsigned& r2, unsigned& r3, unsigned addr) {
    asm volatile("ldmatrix.sync.aligned.m8n8.x4.trans.shared.b16 {%0,%1,%2,%3}, [%4];"
        : "=r"(r0), "=r"(r1), "=r"(r2), "=r"(r3) : "r"(addr));
}
__device__ __forceinline__ void cp16(void* s, const void* g) {
    unsigned a = (unsigned)__cvta_generic_to_shared(s);
    asm volatile("cp.async.cg.shared.global [%0], [%1], 16;" :: "r"(a), "l"(g));
}
__device__ __forceinline__ void cp_commit() { asm volatile("cp.async.commit_group;"); }
template<int N> __device__ __forceinline__ void cp_wait() {
    asm volatile("cp.async.wait_group %0;" :: "n"(N));
}
__device__ __forceinline__ unsigned packh2(float lo, float hi) {
    __half2 h = __floats2half2_rn(lo, hi);
    return *(unsigned*)&h;
}

// ---------------- convert f32 -> half (8 elems/thread) -------------------
__global__ void cvt_h_kernel(const float4* __restrict__ src, __half* __restrict__ dst, long n8) {
    long i = (long)blockIdx.x * blockDim.x + threadIdx.x;
    if (i >= n8) return;
    float4 a = src[i * 2], b = src[i * 2 + 1];
    uint4 o;
    o.x = packh2(a.x, a.y); o.y = packh2(a.z, a.w);
    o.z = packh2(b.x, b.y); o.w = packh2(b.z, b.w);
    *(uint4*)(dst + i * 8) = o;
}

// ---------------- kv concat: [cmem, mem, x] -> g_kvinh (half) ------------
__global__ void concat_h_kernel(const float* __restrict__ x,
                                const float* __restrict__ mem,
                                const float* __restrict__ cmem) {
    long i8 = (long)blockIdx.x * blockDim.x + threadIdx.x;
    if (i8 >= 786432L) return;
    long e = i8 * 8;
    int  b   = (int)(e / (3072L * 1024));
    long rem = e - (long)b * 3072 * 1024;
    int  t   = (int)(rem / 1024);
    int  c   = (int)(rem - (long)t * 1024);
    const float* src;
    if (t < 1024)       src = cmem + (long)b * 1048576 + (long)t * 1024 + c;
    else if (t < 2048)  src = mem  + (long)b * 1048576 + (long)(t - 1024) * 1024 + c;
    else                src = x    + (long)b * 1048576 + (long)(t - 2048) * 1024 + c;
    float4 a = *(const float4*)src, d = *(const float4*)(src + 4);
    uint4 o;
    o.x = packh2(a.x, a.y); o.y = packh2(a.z, a.w);
    o.z = packh2(d.x, d.y); o.w = packh2(d.z, d.w);
    *(uint4*)(g_kvinh + e) = o;
}

// ---------------- transpose + convert: in[R][C] -> out[C][R] half --------
__global__ void thalf_kernel(const float* __restrict__ in, __half* __restrict__ out,
                             int R, int C) {
    __shared__ float t[32][33];
    int bx = blockIdx.x << 5, by = blockIdx.y << 5;
    int tx = threadIdx.x & 31, ty = threadIdx.x >> 5;
    #pragma unroll
    for (int i = 0; i < 4; i++)
        t[ty + i * 8][tx] = in[(long)(by + ty + i * 8) * C + bx + tx];
    __syncthreads();
    #pragma unroll
    for (int i = 0; i < 4; i++)
        out[(long)(bx + ty + i * 8) * R + by + tx] = __float2half_rn(t[tx][ty + i * 8]);
}

// ---------------- conv weight gather: (O,I,4) -> [o][k=r*1024+i] half ----
__global__ void wtt_kernel(const float* __restrict__ w) {
    long idx = (long)blockIdx.x * blockDim.x + threadIdx.x;
    if (idx >= 4194304L) return;
    int o = (int)(idx >> 12), k = (int)(idx & 4095);
    g_wtth[idx] = __float2half_rn(w[((long)o << 12) + ((k & 1023) << 2) + (k >> 10)]);
}

// ---------------- f16 MMA GEMM: C = alpha*A @ Bt^T (+bias) ---------------
template<int OUTH>
__global__ __launch_bounds__(256) void hgemm(
    const __half* __restrict__ A, const __half* __restrict__ Bt,
    const float* __restrict__ bias, void* __restrict__ Cv,
    int K, int lda, int ldb, int ldc, float alpha, long sA, long sC)
{
    extern __shared__ __half hsm[];
    __half (*As)[56] = (__half(*)[56])hsm;                 // [2*128][56]
    __half (*Bs)[56] = (__half(*)[56])(hsm + 2 * 128 * 56);

    int z = blockIdx.z;
    A += (long)z * sA;
    int m0 = blockIdx.y << 7, n0 = blockIdx.x << 7;

    int tid = threadIdx.x, warp = tid >> 5, lane = tid & 31;
    int gid = lane >> 2, tg = lane & 3;
    int wm = warp >> 2, wn = warp & 3;   // WM=64, WN=32

    float acc[4][4][4] = {};

    auto issueT = [&](int k0, int buf) {
        #pragma unroll
        for (int i = 0; i < 2; i++) {
            int f = tid + i * 256;
            int r = f >> 2, c = (f & 3) << 3;
            cp16(&As[buf * 128 + r][c], A + (long)(m0 + r) * lda + k0 + c);
            cp16(&Bs[buf * 128 + r][c], Bt + (long)(n0 + r) * ldb + k0 + c);
        }
        cp_commit();
    };

    issueT(0, 0);
    int nk = K >> 5;
    for (int kt = 0; kt < nk; kt++) {
        int buf = kt & 1;
        if (kt + 1 < nk) {
            __syncthreads();
            issueT((kt + 1) << 5, buf ^ 1);
            cp_wait<1>();
        } else {
            cp_wait<0>();
        }
        __syncthreads();
        #pragma unroll
        for (int ks = 0; ks < 32; ks += 16) {
            unsigned af[4][4], bf[4][2];
            #pragma unroll
            for (int mi = 0; mi < 4; mi++) {
                const __half* ar = &As[buf * 128 + wm * 64 + mi * 16 + gid][ks + 2 * tg];
                af[mi][0] = *(const unsigned*)ar;
                af[mi][1] = *(const unsigned*)(ar + 8 * 56);
                af[mi][2] = *(const unsigned*)(ar + 8);
                af[mi][3] = *(const unsigned*)(ar + 8 * 56 + 8);
            }
            #pragma unroll
            for (int ni = 0; ni < 4; ni++) {
                const __half* br = &Bs[buf * 128 + wn * 32 + ni * 8 + gid][ks + 2 * tg];
                bf[ni][0] = *(const unsigned*)br;
                bf[ni][1] = *(const unsigned*)(br + 8);
            }
            #pragma unroll
            for (int mi = 0; mi < 4; mi++)
                #pragma unroll
                for (int ni = 0; ni < 4; ni++)
                    mma_f16(acc[mi][ni], af[mi], bf[ni][0], bf[ni][1]);
        }
    }

    #pragma unroll
    for (int mi = 0; mi < 4; mi++) {
        #pragma unroll
        for (int ni = 0; ni < 4; ni++) {
            int r0 = m0 + wm * 64 + mi * 16 + gid;
            int c  = n0 + wn * 32 + ni * 8 + 2 * tg;
            if (OUTH) {
                __half* C = (__half*)Cv + (long)z * sC;
                *(unsigned*)(C + (long)r0 * ldc + c) =
                    packh2(alpha * acc[mi][ni][0], alpha * acc[mi][ni][1]);
                *(unsigned*)(C + (long)(r0 + 8) * ldc + c) =
                    packh2(alpha * acc[mi][ni][2], alpha * acc[mi][ni][3]);
            } else {
                float* C = (float*)Cv + (long)z * sC;
                float b0 = 0.f, b1 = 0.f;
                if (bias) { b0 = bias[c]; b1 = bias[c + 1]; }
                *(float2*)(C + (long)r0 * ldc + c) =
                    make_float2(acc[mi][ni][0] + b0, acc[mi][ni][1] + b1);
                *(float2*)(C + (long)(r0 + 8) * ldc + c) =
                    make_float2(acc[mi][ni][2] + b0, acc[mi][ni][3] + b1);
            }
        }
    }
}

// ---------------- fused flash attention, fp16, ldmatrix everywhere --------
// 8 warps, i-tile 128, j-tile 64, grid (1,8,32), 2 CTAs/SM.
// smem (107520 B): Ks[2][64][72]h @0 | Vs[2][64][72]h @18432
//                  Ps[192][72]h @36864 | Pg[128][84]f @64512
#define KS_OFF 0
#define VS_OFF 18432
#define PS_OFF 36864
#define PG_OFF 64512
#define FL_SMEM 107520

__global__ __launch_bounds__(256, 2) void flash_kernel() {
    extern __shared__ __align__(16) unsigned char sm[];
    __half (*Ks)[64][72] = (__half(*)[64][72])(sm + KS_OFF);
    __half (*Vs)[64][72] = (__half(*)[64][72])(sm + VS_OFF);
    __half (*Ps)[72]     = (__half(*)[72])(sm + PS_OFF);
    float  (*Pg)[84]     = (float(*)[84])(sm + PG_OFF);

    int bh = blockIdx.z; int b = bh >> 4, h = bh & 15;
    int i0 = blockIdx.y << 7;
    int tid = threadIdx.x, warp = tid >> 5, lane = tid & 31;
    int gid = lane >> 2, tg = lane & 3;

    // Q fragments (g_qh pre-scaled half)
    unsigned qf[4][4];
    {
        const __half* q0 = g_qh + (long)(b * TT + i0 + (warp << 4) + gid) * DD + h * DHD;
        #pragma unroll
        for (int kb = 0; kb < 4; kb++) {
            qf[kb][0] = *(const unsigned*)(q0 + kb * 16 + 2 * tg);
            qf[kb][1] = *(const unsigned*)(q0 + 8 * DD + kb * 16 + 2 * tg);
            qf[kb][2] = *(const unsigned*)(q0 + kb * 16 + 2 * tg + 8);
            qf[kb][3] = *(const unsigned*)(q0 + 8 * DD + kb * 16 + 2 * tg + 8);
        }
    }

    int r = tid >> 2, q4 = (tid & 3) << 4;
    const __half* kvb = g_kvh + ((long)(b * KVL) + r) * 2048 + h * DHD + q4;
    int ub0 = 896 - i0;

    auto issue = [&](int j0, int buf) {
        const __half* kp = kvb + (long)j0 * 2048;
        cp16(&Ks[buf][r][q4], kp);            cp16(&Ks[buf][r][q4 + 8], kp + 8);
        cp16(&Vs[buf][r][q4], kp + 1024);     cp16(&Vs[buf][r][q4 + 8], kp + 1032);
        int ub = j0 + ub0;
        #pragma unroll
        for (int it = 0; it < 3; it++) {
            int rr = r + it * 64;
            int uu = ub + rr;
            if (uu < KVL) {
                const __half* pp = g_ph + ((long)h * KVL + uu) * 64 + q4;
                cp16(&Ps[rr][q4], pp); cp16(&Ps[rr][q4 + 8], pp + 8);
            } else {
                uint4 z = make_uint4(0, 0, 0, 0);
                *(uint4*)&Ps[rr][q4] = z; *(uint4*)&Ps[rr][q4 + 8] = z;
            }
        }
        cp_commit();
    };

    // ldmatrix lane offsets (row stride 144 B): non-trans B-frag x4 covers
    // 16 n-rows x 16 k-cols = B-fragments of TWO consecutive mmas.
    unsigned frag_off = (lane & 7) * 144 + ((lane >> 3) & 1) * 16 + (lane >> 4) * 1152;
    unsigned kbase = (unsigned)__cvta_generic_to_shared(&Ks[0][0][0]) + frag_off;
    unsigned pbase = (unsigned)__cvta_generic_to_shared(&Ps[0][0]) + frag_off;

    // ldmatrix V addresses (trans)
    int vrow = (lane & 7) + ((lane >> 3) & 1) * 8;
    int vcol = (lane >> 4) * 8;
    unsigned vbase = (unsigned)__cvta_generic_to_shared(&Vs[0][vrow][vcol]);

    float oacc[8][4] = {};
    float m0r = -1e30f, m1r = -1e30f, l0r = 0.f, l1r = 0.f;
    int wb = 112 - (warp << 4);
    int pgr0 = (warp << 4) + gid, pgr1 = pgr0 + 8;
    unsigned pband = pbase + wb * 144;

    issue(0, 0);
    for (int t = 0; t < 48; t++) {
        int buf = t & 1;
        cp_wait<0>();
        __syncthreads();

        // ---- S = QK^T (ldmatrix.x4 B-frags, 2 mmas per load) ----
        float sacc[8][4] = {};
        #pragma unroll
        for (int np = 0; np < 4; np++) {
            #pragma unroll
            for (int kb = 0; kb < 4; kb++) {
                unsigned b0, b1, b2, b3;
                ldsm4(b0, b1, b2, b3, kbase + buf * 9216 + np * 2304 + kb * 32);
                mma_f16(sacc[2 * np],     qf[kb], b0, b1);
                mma_f16(sacc[2 * np + 1], qf[kb], b2, b3);
            }
        }

        // ---- band product: 5 pair-passes, transient pacc ----
        #pragma unroll
        for (int np = 0; np < 5; np++) {
            float pacc[2][4] = {};
            #pragma unroll
            for (int kb = 0; kb < 4; kb++) {
                unsigned b0, b1, b2, b3;
                ldsm4(b0, b1, b2, b3, pband + np * 2304 + kb * 32);
                mma_f16(pacc[0], qf[kb], b0, b1);
                mma_f16(pacc[1], qf[kb], b2, b3);
            }
            int c0 = (2 * np) * 8 + 2 * tg;
            Pg[pgr0][c0]     = pacc[0][0]; Pg[pgr0][c0 + 1] = pacc[0][1];
            Pg[pgr1][c0]     = pacc[0][2]; Pg[pgr1][c0 + 1] = pacc[0][3];
            Pg[pgr0][c0 + 8] = pacc[1][0]; Pg[pgr0][c0 + 9] = pacc[1][1];
            Pg[pgr1][c0 + 8] = pacc[1][2]; Pg[pgr1][c0 + 9] = pacc[1][3];
        }
        __syncthreads();                     // Ks/Ps consumed, Pg visible
        if (t < 47) issue((t + 1) << 6, buf ^ 1);

        // ---- gather shifted band into S ----
        {
            int s0 = 15 - gid, s1 = 7 - gid;
            #pragma unroll
            for (int nb = 0; nb < 8; nb++) {
                int jl = nb * 8 + 2 * tg;
                sacc[nb][0] += Pg[pgr0][jl + s0];
                sacc[nb][1] += Pg[pgr0][jl + 1 + s0];
                sacc[nb][2] += Pg[pgr1][jl + s1];
                sacc[nb][3] += Pg[pgr1][jl + 1 + s1];
            }
        }

        // ---- online softmax (rows quad-local) ----
        float mx0 = -1e30f, mx1 = -1e30f;
        #pragma unroll
        for (int nb = 0; nb < 8; nb++) {
            mx0 = fmaxf(mx0, fmaxf(sacc[nb][0], sacc[nb][1]));
            mx1 = fmaxf(mx1, fmaxf(sacc[nb][2], sacc[nb][3]));
        }
        #pragma unroll
        for (int o = 1; o <= 2; o <<= 1) {
            mx0 = fmaxf(mx0, __shfl_xor_sync(0xffffffffu, mx0, o));
            mx1 = fmaxf(mx1, __shfl_xor_sync(0xffffffffu, mx1, o));
        }
        float mn0 = fmaxf(m0r, mx0), mn1 = fmaxf(m1r, mx1);
        float f0 = __expf(m0r - mn0), f1 = __expf(m1r - mn1);
        m0r = mn0; m1r = mn1;
        float ps0 = 0.f, ps1 = 0.f;
        #pragma unroll
        for (int nb = 0; nb < 8; nb++) {
            sacc[nb][0] = __expf(sacc[nb][0] - mn0);
            sacc[nb][1] = __expf(sacc[nb][1] - mn0);
            sacc[nb][2] = __expf(sacc[nb][2] - mn1);
            sacc[nb][3] = __expf(sacc[nb][3] - mn1);
            ps0 += sacc[nb][0] + sacc[nb][1];
            ps1 += sacc[nb][2] + sacc[nb][3];
            oacc[nb][0] *= f0; oacc[nb][1] *= f0;
            oacc[nb][2] *= f1; oacc[nb][3] *= f1;
        }
        #pragma unroll
        for (int o = 1; o <= 2; o <<= 1) {
            ps0 += __shfl_xor_sync(0xffffffffu, ps0, o);
            ps1 += __shfl_xor_sync(0xffffffffu, ps1, o);
        }
        l0r = l0r * f0 + ps0;
        l1r = l1r * f1 + ps1;

        // ---- AV: probs -> in-register A-frags; V via ldmatrix.trans ----
        #pragma unroll
        for (int kb = 0; kb < 4; kb++) {
            unsigned af[4];
            af[0] = packh2(sacc[2 * kb][0],     sacc[2 * kb][1]);
            af[1] = packh2(sacc[2 * kb][2],     sacc[2 * kb][3]);
            af[2] = packh2(sacc[2 * kb + 1][0], sacc[2 * kb + 1][1]);
            af[3] = packh2(sacc[2 * kb + 1][2], sacc[2 * kb + 1][3]);
            unsigned va = vbase + buf * 9216 + kb * 2304;
            #pragma unroll
            for (int p = 0; p < 4; p++) {
                unsigned b0, b1, b2, b3;
                ldsm4t(b0, b1, b2, b3, va + p * 32);
                mma_f16(oacc[2 * p],     af, b0, b1);
                mma_f16(oacc[2 * p + 1], af, b2, b3);
            }
        }
    }

    // ---- write ctx = O / l as half ----
    float inv0 = 1.0f / l0r, inv1 = 1.0f / l1r;
    #pragma unroll
    for (int nb = 0; nb < 8; nb++) {
        int c = h * DHD + nb * 8 + 2 * tg;
        long r0 = (long)(b * TT + i0 + (warp << 4) + gid) * DD + c;
        *(unsigned*)(g_ctxh + r0)          = packh2(oacc[nb][0] * inv0, oacc[nb][1] * inv0);
        *(unsigned*)(g_ctxh + r0 + 8 * DD) = packh2(oacc[nb][2] * inv1, oacc[nb][3] * inv1);
    }
}

// ---------------- copies + aux -------------------------------------------
__global__ void copy4_kernel(const float4* __restrict__ src, float4* __restrict__ dst, long n4) {
    long i = (long)blockIdx.x * blockDim.x + threadIdx.x;
    if (i < n4) dst[i] = src[i];
}
__global__ void aux_kernel(float* out) { *out = 0.f; }

// ---------------- launch ---------------------------------------------------
extern "C" void kernel_launch(void* const* d_in, const int* in_sizes, int n_in,
                              void* d_out_, int out_size) {
    const float* x      = (const float*)d_in[0];
    const float* mem    = (const float*)d_in[1];
    const float* cmem   = (const float*)d_in[2];
    const float* pos    = (const float*)d_in[3];
    const float* Wq     = (const float*)d_in[4];
    const float* Wkv    = (const float*)d_in[5];
    const float* Wout   = (const float*)d_in[6];
    const float* b_out  = (const float*)d_in[7];
    const float* conv_w = (const float*)d_in[8];
    const float* conv_b = (const float*)d_in[9];
    float* out = (float*)d_out_;

    __half *p_ph, *p_kvinh, *p_qh, *p_kvh, *p_ctxh;
    __half *p_wqth, *p_wkvth, *p_wouth, *p_wtth;
    cudaGetSymbolAddress((void**)&p_ph,    g_ph);
    cudaGetSymbolAddress((void**)&p_kvinh, g_kvinh);
    cudaGetSymbolAddress((void**)&p_qh,    g_qh);
    cudaGetSymbolAddress((void**)&p_kvh,   g_kvh);
    cudaGetSymbolAddress((void**)&p_ctxh,  g_ctxh);
    cudaGetSymbolAddress((void**)&p_wqth,  g_wqth);
    cudaGetSymbolAddress((void**)&p_wkvth, g_wkvth);
    cudaGetSymbolAddress((void**)&p_wouth, g_wouth);
    cudaGetSymbolAddress((void**)&p_wtth,  g_wtth);

    cudaFuncSetAttribute(flash_kernel, cudaFuncAttributeMaxDynamicSharedMemorySize, FL_SMEM);
    cudaFuncSetAttribute(hgemm<0>, cudaFuncAttributeMaxDynamicSharedMemorySize, 57344);
    cudaFuncSetAttribute(hgemm<1>, cudaFuncAttributeMaxDynamicSharedMemorySize, 57344);

    // pre-convert to half
    concat_h_kernel<<<3072, 256>>>(x, mem, cmem);
    cvt_h_kernel<<<1536, 256>>>((const float4*)pos, p_ph, 393216);
    thalf_kernel<<<dim3(32, 32), 256>>>(Wq,   p_wqth,  1024, 1024);
    thalf_kernel<<<dim3(64, 32), 256>>>(Wkv,  p_wkvth, 1024, 2048);
    thalf_kernel<<<dim3(32, 32), 256>>>(Wout, p_wouth, 1024, 1024);
    wtt_kernel<<<16384, 256>>>(conv_w);

    // q = SCALE * x @ Wq  (x rows live in g_kvinh at offset 2048 per batch)
    hgemm<1><<<dim3(8, 8, 2), 256, 57344>>>(
        p_kvinh + 2048L * 1024, p_wqth, nullptr, p_qh,
        1024, 1024, 1024, 1024, SCALE_F, 3072L * 1024, 1024L * 1024);
    // kv = kv_in @ Wkv  (half out)
    hgemm<1><<<dim3(16, 48, 1), 256, 57344>>>(
        p_kvinh, p_wkvth, nullptr, p_kvh, 1024, 1024, 1024, 2048, 1.0f, 0, 0);

    // fused attention
    flash_kernel<<<dim3(1, 8, 32), 256, FL_SMEM>>>();

    // logits = ctx @ Wout + b_out (f32)
    hgemm<0><<<dim3(8, 16, 1), 256, 57344>>>(
        p_ctxh, p_wouth, b_out, out, 1024, 1024, 1024, 1024, 1.0f, 0, 0);

    // new_mem = x (f32 copy)
    copy4_kernel<<<2048, 256>>>((const float4*)x, (float4*)(out + 2097152), 524288);

    // new_cmem part 1: cmem[:, 256:]
    copy4_kernel<<<768, 256>>>((const float4*)(cmem + 262144),  (float4*)(out + 4194304), 196608);
    copy4_kernel<<<768, 256>>>((const float4*)(cmem + 1310720), (float4*)(out + 5242880), 196608);

    // new_cmem part 2: conv as GEMM (mem rows live in g_kvinh at offset 1024)
    hgemm<0><<<dim3(8, 2, 2), 256, 57344>>>(
        p_kvinh + 1024L * 1024, p_wtth, conv_b, out + 4980736,
        4096, 4096, 4096, 1024, 1.0f, 3072L * 1024, 1048576L);

    // aux_loss = 0
    aux_kernel<<<1, 1>>>(out + 6291456);
}

// round 13
// speedup vs baseline: 2.4921x; 1.0786x over previous
#include <cuda_runtime.h>
#include <cuda_fp16.h>

// Problem constants
#define BQ   2
#define TT   1024
#define DD   1024
#define HH   16
#define DHD  64
#define KVL  3072
#define MEML 1024
#define SCALE_F 0.125f

// ---------------- scratch (device globals; no allocation) ----------------
__device__ __half g_ph   [16L * 3072 * 64];
__device__ __half g_kvinh[6144L * 1024];     // [cmem|mem|x] per batch, half
__device__ __half g_qh   [2048L * 1024];     // pre-scaled by SCALE
__device__ __half g_kvh  [6144L * 2048];     // K cols 0..1023, V cols 1024..2047
__device__ __half g_ctxh [2048L * 1024];
__device__ __half g_wqth [1024L * 1024];     // Wq^T
__device__ __half g_wkvth[2048L * 1024];     // Wkv^T
__device__ __half g_wouth[1024L * 1024];     // Wout^T
__device__ __half g_wtth [1024L * 4096];     // conv weight [o][k]

// ---------------- helpers ------------------------------------------------
__device__ __forceinline__ void mma_f16(float c[4], const unsigned a[4],
                                        unsigned b0, unsigned b1) {
    asm volatile(
        "mma.sync.aligned.m16n8k16.row.col.f32.f16.f16.f32 "
        "{%0,%1,%2,%3},{%4,%5,%6,%7},{%8,%9},{%0,%1,%2,%3};"
        : "+f"(c[0]), "+f"(c[1]), "+f"(c[2]), "+f"(c[3])
        : "r"(a[0]), "r"(a[1]), "r"(a[2]), "r"(a[3]), "r"(b0), "r"(b1));
}
__device__ __forceinline__ void ldsm4(unsigned& r0, unsigned& r1,
                                      unsigned& r2, unsigned& r3, unsigned addr) {
    asm volatile("ldmatrix.sync.aligned.m8n8.x4.shared.b16 {%0,%1,%2,%3}, [%4];"
        : "=r"(r0), "=r"(r1), "=r"(r2), "=r"(r3) : "r"(addr));
}
__device__ __forceinline__ void ldsm4t(unsigned& r0, unsigned& r1,
                                       unsigned& r2, unsigned& r3, unsigned addr) {
    asm volatile("ldmatrix.sync.aligned.m8n8.x4.trans.shared.b16 {%0,%1,%2,%3}, [%4];"
        : "=r"(r0), "=r"(r1), "=r"(r2), "=r"(r3) : "r"(addr));
}
__device__ __forceinline__ void cp16(void* s, const void* g) {
    unsigned a = (unsigned)__cvta_generic_to_shared(s);
    asm volatile("cp.async.cg.shared.global [%0], [%1], 16;" :: "r"(a), "l"(g));
}
__device__ __forceinline__ void cp_commit() { asm volatile("cp.async.commit_group;"); }
template<int N> __device__ __forceinline__ void cp_wait() {
    asm volatile("cp.async.wait_group %0;" :: "n"(N));
}
__device__ __forceinline__ unsigned packh2(float lo, float hi) {
    __half2 h = __floats2half2_rn(lo, hi);
    return *(unsigned*)&h;
}

// ---------------- convert f32 -> half (8 elems/thread) -------------------
__global__ void cvt_h_kernel(const float4* __restrict__ src, __half* __restrict__ dst, long n8) {
    long i = (long)blockIdx.x * blockDim.x + threadIdx.x;
    if (i >= n8) return;
    float4 a = src[i * 2], b = src[i * 2 + 1];
    uint4 o;
    o.x = packh2(a.x, a.y); o.y = packh2(a.z, a.w);
    o.z = packh2(b.x, b.y); o.w = packh2(b.z, b.w);
    *(uint4*)(dst + i * 8) = o;
}

// ---------------- kv concat: [cmem, mem, x] -> g_kvinh (half) ------------
__global__ void concat_h_kernel(const float* __restrict__ x,
                                const float* __restrict__ mem,
                                const float* __restrict__ cmem) {
    long i8 = (long)blockIdx.x * blockDim.x + threadIdx.x;
    if (i8 >= 786432L) return;
    long e = i8 * 8;
    int  b   = (int)(e / (3072L * 1024));
    long rem = e - (long)b * 3072 * 1024;
    int  t   = (int)(rem / 1024);
    int  c   = (int)(rem - (long)t * 1024);
    const float* src;
    if (t < 1024)       src = cmem + (long)b * 1048576 + (long)t * 1024 + c;
    else if (t < 2048)  src = mem  + (long)b * 1048576 + (long)(t - 1024) * 1024 + c;
    else                src = x    + (long)b * 1048576 + (long)(t - 2048) * 1024 + c;
    float4 a = *(const float4*)src, d = *(const float4*)(src + 4);
    uint4 o;
    o.x = packh2(a.x, a.y); o.y = packh2(a.z, a.w);
    o.z = packh2(d.x, d.y); o.w = packh2(d.z, d.w);
    *(uint4*)(g_kvinh + e) = o;
}

// ---------------- batched transpose+convert: W[R][C] -> out[C][R] half ----
__global__ void thalf3_kernel(const float* __restrict__ Wq,
                              const float* __restrict__ Wkv,
                              const float* __restrict__ Wout) {
    int z = blockIdx.z;
    const float* in = (z == 0) ? Wq : (z == 1 ? Wkv : Wout);
    __half* out = (z == 0) ? g_wqth : (z == 1 ? g_wkvth : g_wouth);
    int C = (z == 1) ? 2048 : 1024;
    int bx = blockIdx.x << 5, by = blockIdx.y << 5;
    if (bx >= C) return;
    __shared__ float t[32][33];
    int tx = threadIdx.x & 31, ty = threadIdx.x >> 5;
    #pragma unroll
    for (int i = 0; i < 4; i++)
        t[ty + i * 8][tx] = in[(long)(by + ty + i * 8) * C + bx + tx];
    __syncthreads();
    #pragma unroll
    for (int i = 0; i < 4; i++)
        out[(long)(bx + ty + i * 8) * 1024 + by + tx] = __float2half_rn(t[tx][ty + i * 8]);
}

// ---------------- conv weight gather: (O,I,4) -> [o][k=r*1024+i] half ----
__global__ void wtt_kernel(const float* __restrict__ w) {
    long idx = (long)blockIdx.x * blockDim.x + threadIdx.x;
    if (idx >= 4194304L) return;
    int o = (int)(idx >> 12), k = (int)(idx & 4095);
    g_wtth[idx] = __float2half_rn(w[((long)o << 12) + ((k & 1023) << 2) + (k >> 10)]);
}

// ---------------- f16 MMA GEMM: C = alpha*A @ Bt^T (+bias) ---------------
template<int OUTH>
__global__ __launch_bounds__(256) void hgemm(
    const __half* __restrict__ A, const __half* __restrict__ Bt,
    const float* __restrict__ bias, void* __restrict__ Cv,
    int K, int lda, int ldb, int ldc, float alpha, long sA, long sC)
{
    extern __shared__ __half hsm[];
    __half (*As)[56] = (__half(*)[56])hsm;                 // [2*128][56]
    __half (*Bs)[56] = (__half(*)[56])(hsm + 2 * 128 * 56);

    int z = blockIdx.z;
    A += (long)z * sA;
    int m0 = blockIdx.y << 7, n0 = blockIdx.x << 7;

    int tid = threadIdx.x, warp = tid >> 5, lane = tid & 31;
    int gid = lane >> 2, tg = lane & 3;
    int wm = warp >> 2, wn = warp & 3;   // WM=64, WN=32

    float acc[4][4][4] = {};

    auto issueT = [&](int k0, int buf) {
        #pragma unroll
        for (int i = 0; i < 2; i++) {
            int f = tid + i * 256;
            int r = f >> 2, c = (f & 3) << 3;
            cp16(&As[buf * 128 + r][c], A + (long)(m0 + r) * lda + k0 + c);
            cp16(&Bs[buf * 128 + r][c], Bt + (long)(n0 + r) * ldb + k0 + c);
        }
        cp_commit();
    };

    issueT(0, 0);
    int nk = K >> 5;
    for (int kt = 0; kt < nk; kt++) {
        int buf = kt & 1;
        if (kt + 1 < nk) {
            __syncthreads();
            issueT((kt + 1) << 5, buf ^ 1);
            cp_wait<1>();
        } else {
            cp_wait<0>();
        }
        __syncthreads();
        #pragma unroll
        for (int ks = 0; ks < 32; ks += 16) {
            unsigned af[4][4], bf[4][2];
            #pragma unroll
            for (int mi = 0; mi < 4; mi++) {
                const __half* ar = &As[buf * 128 + wm * 64 + mi * 16 + gid][ks + 2 * tg];
                af[mi][0] = *(const unsigned*)ar;
                af[mi][1] = *(const unsigned*)(ar + 8 * 56);
                af[mi][2] = *(const unsigned*)(ar + 8);
                af[mi][3] = *(const unsigned*)(ar + 8 * 56 + 8);
            }
            #pragma unroll
            for (int ni = 0; ni < 4; ni++) {
                const __half* br = &Bs[buf * 128 + wn * 32 + ni * 8 + gid][ks + 2 * tg];
                bf[ni][0] = *(const unsigned*)br;
                bf[ni][1] = *(const unsigned*)(br + 8);
            }
            #pragma unroll
            for (int mi = 0; mi < 4; mi++)
                #pragma unroll
                for (int ni = 0; ni < 4; ni++)
                    mma_f16(acc[mi][ni], af[mi], bf[ni][0], bf[ni][1]);
        }
    }

    #pragma unroll
    for (int mi = 0; mi < 4; mi++) {
        #pragma unroll
        for (int ni = 0; ni < 4; ni++) {
            int r0 = m0 + wm * 64 + mi * 16 + gid;
            int c  = n0 + wn * 32 + ni * 8 + 2 * tg;
            if (OUTH) {
                __half* C = (__half*)Cv + (long)z * sC;
                *(unsigned*)(C + (long)r0 * ldc + c) =
                    packh2(alpha * acc[mi][ni][0], alpha * acc[mi][ni][1]);
                *(unsigned*)(C + (long)(r0 + 8) * ldc + c) =
                    packh2(alpha * acc[mi][ni][2], alpha * acc[mi][ni][3]);
            } else {
                float* C = (float*)Cv + (long)z * sC;
                float b0 = 0.f, b1 = 0.f;
                if (bias) { b0 = bias[c]; b1 = bias[c + 1]; }
                *(float2*)(C + (long)r0 * ldc + c) =
                    make_float2(acc[mi][ni][0] + b0, acc[mi][ni][1] + b1);
                *(float2*)(C + (long)(r0 + 8) * ldc + c) =
                    make_float2(acc[mi][ni][2] + b0, acc[mi][ni][3] + b1);
            }
        }
    }
}

// ---------------- fused flash attention, fp16, pos ring buffer ------------
// 8 warps, i-tile 128, j-tile 64, grid (1,8,32), 2 CTAs/SM.
// smem (96256 B): Ks[2][64][72]h @0 | Vs[2][64][72]h @18432
//                 Ps[256][72]h ring @36864 | PgH[128][88]h @73728
#define KS_OFF 0
#define VS_OFF 18432
#define PS_OFF 36864
#define PG_OFF 73728
#define FL_SMEM 96256

__global__ __launch_bounds__(256, 2) void flash_kernel() {
    extern __shared__ __align__(16) unsigned char sm[];
    __half (*Ks)[64][72] = (__half(*)[64][72])(sm + KS_OFF);
    __half (*Vs)[64][72] = (__half(*)[64][72])(sm + VS_OFF);
    __half (*Ps)[72]     = (__half(*)[72])(sm + PS_OFF);      // 256-row ring
    __half (*Pg)[88]     = (__half(*)[88])(sm + PG_OFF);

    int bh = blockIdx.z; int b = bh >> 4, h = bh & 15;
    int i0 = blockIdx.y << 7;
    int tid = threadIdx.x, warp = tid >> 5, lane = tid & 31;
    int gid = lane >> 2, tg = lane & 3;

    // Q fragments (g_qh pre-scaled half)
    unsigned qf[4][4];
    {
        const __half* q0 = g_qh + (long)(b * TT + i0 + (warp << 4) + gid) * DD + h * DHD;
        #pragma unroll
        for (int kb = 0; kb < 4; kb++) {
            qf[kb][0] = *(const unsigned*)(q0 + kb * 16 + 2 * tg);
            qf[kb][1] = *(const unsigned*)(q0 + 8 * DD + kb * 16 + 2 * tg);
            qf[kb][2] = *(const unsigned*)(q0 + kb * 16 + 2 * tg + 8);
            qf[kb][3] = *(const unsigned*)(q0 + 8 * DD + kb * 16 + 2 * tg + 8);
        }
    }

    int r = tid >> 2, q4 = (tid & 3) << 4;
    const __half* kvb = g_kvh + ((long)(b * KVL) + r) * 2048 + h * DHD + q4;
    int ub0 = 896 - i0;                      // pos idx of ring-logical row 0 at j0=0

    // load one pos row (pos_idx uu) into ring slot uu&255
    auto loadP = [&](int uu) {
        int phys = uu & 255;
        if (uu < KVL) {
            const __half* pp = g_ph + ((long)h * KVL + uu) * 64 + q4;
            cp16(&Ps[phys][q4], pp); cp16(&Ps[phys][q4 + 8], pp + 8);
        } else {
            uint4 z = make_uint4(0, 0, 0, 0);
            *(uint4*)&Ps[phys][q4] = z; *(uint4*)&Ps[phys][q4 + 8] = z;
        }
    };

    auto issue = [&](int j0, int buf, bool first) {
        const __half* kp = kvb + (long)j0 * 2048;
        cp16(&Ks[buf][r][q4], kp);            cp16(&Ks[buf][r][q4 + 8], kp + 8);
        cp16(&Vs[buf][r][q4], kp + 1024);     cp16(&Vs[buf][r][q4 + 8], kp + 1032);
        int ub = j0 + ub0;
        if (first) {
            loadP(ub + r); loadP(ub + r + 64); loadP(ub + r + 128);
        } else {
            loadP(ub + r + 128);             // only the 64 new rows
        }
        cp_commit();
    };

    // ldmatrix lane offsets (row stride 144 B)
    unsigned frag_off = (lane & 7) * 144 + ((lane >> 3) & 1) * 16 + (lane >> 4) * 1152;
    unsigned kbase = (unsigned)__cvta_generic_to_shared(&Ks[0][0][0]) + frag_off;
    unsigned psbase = (unsigned)__cvta_generic_to_shared(&Ps[0][0]);
    int lanerow = (lane & 7) + ((lane >> 4) << 3);       // row within 16-row window
    unsigned pcol = ((lane >> 3) & 1) << 4;              // 16-byte col half

    // ldmatrix V addresses (trans)
    int vrow = (lane & 7) + ((lane >> 3) & 1) * 8;
    int vcol = (lane >> 4) * 8;
    unsigned vbase = (unsigned)__cvta_generic_to_shared(&Vs[0][vrow][vcol]);

    float oacc[8][4] = {};
    float m0r = -1e30f, m1r = -1e30f, l0r = 0.f, l1r = 0.f;
    int wb = 112 - (warp << 4);
    int pgr0 = (warp << 4) + gid, pgr1 = pgr0 + 8;
    int prow_base = ub0 + wb + lanerow;      // + j0 + np*16, then &255

    issue(0, 0, true);
    for (int t = 0; t < 48; t++) {
        int buf = t & 1;
        cp_wait<0>();
        __syncthreads();

        // ---- S = QK^T (ldmatrix.x4 B-frags, 2 mmas per load) ----
        float sacc[8][4] = {};
        #pragma unroll
        for (int np = 0; np < 4; np++) {
            #pragma unroll
            for (int kb = 0; kb < 4; kb++) {
                unsigned b0, b1, b2, b3;
                ldsm4(b0, b1, b2, b3, kbase + buf * 9216 + np * 2304 + kb * 32);
                mma_f16(sacc[2 * np],     qf[kb], b0, b1);
                mma_f16(sacc[2 * np + 1], qf[kb], b2, b3);
            }
        }

        // ---- band product from ring: 5 pair-passes ----
        int pr = prow_base + (t << 6);
        #pragma unroll
        for (int np = 0; np < 5; np++) {
            float pacc[2][4] = {};
            unsigned pa = psbase + (unsigned)((pr + np * 16) & 255) * 144 + pcol;
            #pragma unroll
            for (int kb = 0; kb < 4; kb++) {
                unsigned b0, b1, b2, b3;
                ldsm4(b0, b1, b2, b3, pa + kb * 32);
                mma_f16(pacc[0], qf[kb], b0, b1);
                mma_f16(pacc[1], qf[kb], b2, b3);
            }
            int c0 = (2 * np) * 8 + 2 * tg;
            *(unsigned*)&Pg[pgr0][c0]     = packh2(pacc[0][0], pacc[0][1]);
            *(unsigned*)&Pg[pgr1][c0]     = packh2(pacc[0][2], pacc[0][3]);
            *(unsigned*)&Pg[pgr0][c0 + 8] = packh2(pacc[1][0], pacc[1][1]);
            *(unsigned*)&Pg[pgr1][c0 + 8] = packh2(pacc[1][2], pacc[1][3]);
        }
        __syncthreads();                     // Ks/Ps consumed, Pg visible
        if (t < 47) issue((t + 1) << 6, buf ^ 1, false);

        // ---- gather shifted band into S ----
        {
            int s0 = 15 - gid, s1 = 7 - gid;
            #pragma unroll
            for (int nb = 0; nb < 8; nb++) {
                int jl = nb * 8 + 2 * tg;
                sacc[nb][0] += __half2float(Pg[pgr0][jl + s0]);
                sacc[nb][1] += __half2float(Pg[pgr0][jl + 1 + s0]);
                sacc[nb][2] += __half2float(Pg[pgr1][jl + s1]);
                sacc[nb][3] += __half2float(Pg[pgr1][jl + 1 + s1]);
            }
        }

        // ---- online softmax (rows quad-local) ----
        float mx0 = -1e30f, mx1 = -1e30f;
        #pragma unroll
        for (int nb = 0; nb < 8; nb++) {
            mx0 = fmaxf(mx0, fmaxf(sacc[nb][0], sacc[nb][1]));
            mx1 = fmaxf(mx1, fmaxf(sacc[nb][2], sacc[nb][3]));
        }
        #pragma unroll
        for (int o = 1; o <= 2; o <<= 1) {
            mx0 = fmaxf(mx0, __shfl_xor_sync(0xffffffffu, mx0, o));
            mx1 = fmaxf(mx1, __shfl_xor_sync(0xffffffffu, mx1, o));
        }
        float mn0 = fmaxf(m0r, mx0), mn1 = fmaxf(m1r, mx1);
        float f0 = __expf(m0r - mn0), f1 = __expf(m1r - mn1);
        m0r = mn0; m1r = mn1;
        float ps0 = 0.f, ps1 = 0.f;
        #pragma unroll
        for (int nb = 0; nb < 8; nb++) {
            sacc[nb][0] = __expf(sacc[nb][0] - mn0);
            sacc[nb][1] = __expf(sacc[nb][1] - mn0);
            sacc[nb][2] = __expf(sacc[nb][2] - mn1);
            sacc[nb][3] = __expf(sacc[nb][3] - mn1);
            ps0 += sacc[nb][0] + sacc[nb][1];
            ps1 += sacc[nb][2] + sacc[nb][3];
            oacc[nb][0] *= f0; oacc[nb][1] *= f0;
            oacc[nb][2] *= f1; oacc[nb][3] *= f1;
        }
        #pragma unroll
        for (int o = 1; o <= 2; o <<= 1) {
            ps0 += __shfl_xor_sync(0xffffffffu, ps0, o);
            ps1 += __shfl_xor_sync(0xffffffffu, ps1, o);
        }
        l0r = l0r * f0 + ps0;
        l1r = l1r * f1 + ps1;

        // ---- AV: probs -> in-register A-frags; V via ldmatrix.trans ----
        #pragma unroll
        for (int kb = 0; kb < 4; kb++) {
            unsigned af[4];
            af[0] = packh2(sacc[2 * kb][0],     sacc[2 * kb][1]);
            af[1] = packh2(sacc[2 * kb][2],     sacc[2 * kb][3]);
            af[2] = packh2(sacc[2 * kb + 1][0], sacc[2 * kb + 1][1]);
            af[3] = packh2(sacc[2 * kb + 1][2], sacc[2 * kb + 1][3]);
            unsigned va = vbase + buf * 9216 + kb * 2304;
            #pragma unroll
            for (int p = 0; p < 4; p++) {
                unsigned b0, b1, b2, b3;
                ldsm4t(b0, b1, b2, b3, va + p * 32);
                mma_f16(oacc[2 * p],     af, b0, b1);
                mma_f16(oacc[2 * p + 1], af, b2, b3);
            }
        }
    }

    // ---- write ctx = O / l as half ----
    float inv0 = 1.0f / l0r, inv1 = 1.0f / l1r;
    #pragma unroll
    for (int nb = 0; nb < 8; nb++) {
        int c = h * DHD + nb * 8 + 2 * tg;
        long r0 = (long)(b * TT + i0 + (warp << 4) + gid) * DD + c;
        *(unsigned*)(g_ctxh + r0)          = packh2(oacc[nb][0] * inv0, oacc[nb][1] * inv0);
        *(unsigned*)(g_ctxh + r0 + 8 * DD) = packh2(oacc[nb][2] * inv1, oacc[nb][3] * inv1);
    }
}

// ---------------- copies + aux -------------------------------------------
__global__ void copy4_kernel(const float4* __restrict__ src, float4* __restrict__ dst, long n4) {
    long i = (long)blockIdx.x * blockDim.x + threadIdx.x;
    if (i < n4) dst[i] = src[i];
}
__global__ void aux_kernel(float* out) { *out = 0.f; }

// ---------------- launch ---------------------------------------------------
extern "C" void kernel_launch(void* const* d_in, const int* in_sizes, int n_in,
                              void* d_out_, int out_size) {
    const float* x      = (const float*)d_in[0];
    const float* mem    = (const float*)d_in[1];
    const float* cmem   = (const float*)d_in[2];
    const float* pos    = (const float*)d_in[3];
    const float* Wq     = (const float*)d_in[4];
    const float* Wkv    = (const float*)d_in[5];
    const float* Wout   = (const float*)d_in[6];
    const float* b_out  = (const float*)d_in[7];
    const float* conv_w = (const float*)d_in[8];
    const float* conv_b = (const float*)d_in[9];
    float* out = (float*)d_out_;

    __half *p_ph, *p_kvinh, *p_qh, *p_kvh, *p_ctxh;
    __half *p_wqth, *p_wkvth, *p_wouth, *p_wtth;
    cudaGetSymbolAddress((void**)&p_ph,    g_ph);
    cudaGetSymbolAddress((void**)&p_kvinh, g_kvinh);
    cudaGetSymbolAddress((void**)&p_qh,    g_qh);
    cudaGetSymbolAddress((void**)&p_kvh,   g_kvh);
    cudaGetSymbolAddress((void**)&p_ctxh,  g_ctxh);
    cudaGetSymbolAddress((void**)&p_wqth,  g_wqth);
    cudaGetSymbolAddress((void**)&p_wkvth, g_wkvth);
    cudaGetSymbolAddress((void**)&p_wouth, g_wouth);
    cudaGetSymbolAddress((void**)&p_wtth,  g_wtth);

    cudaFuncSetAttribute(flash_kernel, cudaFuncAttributeMaxDynamicSharedMemorySize, FL_SMEM);
    cudaFuncSetAttribute(hgemm<0>, cudaFuncAttributeMaxDynamicSharedMemorySize, 57344);
    cudaFuncSetAttribute(hgemm<1>, cudaFuncAttributeMaxDynamicSharedMemorySize, 57344);

    // pre-convert to half
    concat_h_kernel<<<3072, 256>>>(x, mem, cmem);
    cvt_h_kernel<<<1536, 256>>>((const float4*)pos, p_ph, 393216);
    thalf3_kernel<<<dim3(64, 32, 3), 256>>>(Wq, Wkv, Wout);
    wtt_kernel<<<16384, 256>>>(conv_w);

    // q = SCALE * x @ Wq  (x rows live in g_kvinh at offset 2048 per batch)
    hgemm<1><<<dim3(8, 8, 2), 256, 57344>>>(
        p_kvinh + 2048L * 1024, p_wqth, nullptr, p_qh,
        1024, 1024, 1024, 1024, SCALE_F, 3072L * 1024, 1024L * 1024);
    // kv = kv_in @ Wkv  (half out)
    hgemm<1><<<dim3(16, 48, 1), 256, 57344>>>(
        p_kvinh, p_wkvth, nullptr, p_kvh, 1024, 1024, 1024, 2048, 1.0f, 0, 0);

    // fused attention
    flash_kernel<<<dim3(1, 8, 32), 256, FL_SMEM>>>();

    // logits = ctx @ Wout + b_out (f32)
    hgemm<0><<<dim3(8, 16, 1), 256, 57344>>>(
        p_ctxh, p_wouth, b_out, out, 1024, 1024, 1024, 1024, 1.0f, 0, 0);

    // new_mem = x (f32 copy)
    copy4_kernel<<<2048, 256>>>((const float4*)x, (float4*)(out + 2097152), 524288);

    // new_cmem part 1: cmem[:, 256:]
    copy4_kernel<<<768, 256>>>((const float4*)(cmem + 262144),  (float4*)(out + 4194304), 196608);
    copy4_kernel<<<768, 256>>>((const float4*)(cmem + 1310720), (float4*)(out + 5242880), 196608);

    // new_cmem part 2: conv as GEMM (mem rows live in g_kvinh at offset 1024)
    hgemm<0><<<dim3(8, 2, 2), 256, 57344>>>(
        p_kvinh + 1024L * 1024, p_wtth, conv_b, out + 4980736,
        4096, 4096, 4096, 1024, 1.0f, 3072L * 1024, 1048576L);

    // aux_loss = 0
    aux_kernel<<<1, 1>>>(out + 6291456);
}

// round 16
// speedup vs baseline: 2.5517x; 1.0239x over previous
#include <cuda_runtime.h>
#include <cuda_fp16.h>

// Problem constants
#define BQ   2
#define TT   1024
#define DD   1024
#define HH   16
#define DHD  64
#define KVL  3072
#define MEML 1024
#define SCALE_F 0.125f

// ---------------- scratch (device globals; no allocation) ----------------
__device__ __half g_ph   [16L * 3072 * 64];
__device__ __half g_kvinh[6144L * 1024];     // [cmem|mem|x] per batch, half
__device__ __half g_qh   [2048L * 1024];     // pre-scaled by SCALE
__device__ __half g_kvh  [6144L * 2048];     // K cols 0..1023, V cols 1024..2047
__device__ __half g_ctxh [2048L * 1024];
__device__ __half g_wqth [1024L * 1024];     // Wq^T
__device__ __half g_wkvth[2048L * 1024];     // Wkv^T
__device__ __half g_wouth[1024L * 1024];     // Wout^T
__device__ __half g_wtth [1024L * 4096];     // conv weight [o][k]

// ---------------- helpers ------------------------------------------------
__device__ __forceinline__ void mma_f16(float c[4], const unsigned a[4],
                                        unsigned b0, unsigned b1) {
    asm volatile(
        "mma.sync.aligned.m16n8k16.row.col.f32.f16.f16.f32 "
        "{%0,%1,%2,%3},{%4,%5,%6,%7},{%8,%9},{%0,%1,%2,%3};"
        : "+f"(c[0]), "+f"(c[1]), "+f"(c[2]), "+f"(c[3])
        : "r"(a[0]), "r"(a[1]), "r"(a[2]), "r"(a[3]), "r"(b0), "r"(b1));
}
__device__ __forceinline__ void ldsm4(unsigned& r0, unsigned& r1,
                                      unsigned& r2, unsigned& r3, unsigned addr) {
    asm volatile("ldmatrix.sync.aligned.m8n8.x4.shared.b16 {%0,%1,%2,%3}, [%4];"
        : "=r"(r0), "=r"(r1), "=r"(r2), "=r"(r3) : "r"(addr));
}
__device__ __forceinline__ void ldsm4t(unsigned& r0, unsigned& r1,
                                       unsigned& r2, unsigned& r3, unsigned addr) {
    asm volatile("ldmatrix.sync.aligned.m8n8.x4.trans.shared.b16 {%0,%1,%2,%3}, [%4];"
        : "=r"(r0), "=r"(r1), "=r"(r2), "=r"(r3) : "r"(addr));
}
__device__ __forceinline__ void cp16(void* s, const void* g) {
    unsigned a = (unsigned)__cvta_generic_to_shared(s);
    asm volatile("cp.async.cg.shared.global [%0], [%1], 16;" :: "r"(a), "l"(g));
}
__device__ __forceinline__ void cp_commit() { asm volatile("cp.async.commit_group;"); }
template<int N> __device__ __forceinline__ void cp_wait() {
    asm volatile("cp.async.wait_group %0;" :: "n"(N));
}
__device__ __forceinline__ unsigned packh2(float lo, float hi) {
    __half2 h = __floats2half2_rn(lo, hi);
    return *(unsigned*)&h;
}

// ---------------- convert f32 -> half (8 elems/thread) -------------------
__global__ void cvt_h_kernel(const float4* __restrict__ src, __half* __restrict__ dst, long n8) {
    long i = (long)blockIdx.x * blockDim.x + threadIdx.x;
    if (i >= n8) return;
    float4 a = src[i * 2], b = src[i * 2 + 1];
    uint4 o;
    o.x = packh2(a.x, a.y); o.y = packh2(a.z, a.w);
    o.z = packh2(b.x, b.y); o.w = packh2(b.z, b.w);
    *(uint4*)(dst + i * 8) = o;
}

// ---------------- kv concat: [cmem, mem, x] -> g_kvinh (half) ------------
__global__ void concat_h_kernel(const float* __restrict__ x,
                                const float* __restrict__ mem,
                                const float* __restrict__ cmem) {
    long i8 = (long)blockIdx.x * blockDim.x + threadIdx.x;
    if (i8 >= 786432L) return;
    long e = i8 * 8;
    int  b   = (int)(e / (3072L * 1024));
    long rem = e - (long)b * 3072 * 1024;
    int  t   = (int)(rem / 1024);
    int  c   = (int)(rem - (long)t * 1024);
    const float* src;
    if (t < 1024)       src = cmem + (long)b * 1048576 + (long)t * 1024 + c;
    else if (t < 2048)  src = mem  + (long)b * 1048576 + (long)(t - 1024) * 1024 + c;
    else                src = x    + (long)b * 1048576 + (long)(t - 2048) * 1024 + c;
    float4 a = *(const float4*)src, d = *(const float4*)(src + 4);
    uint4 o;
    o.x = packh2(a.x, a.y); o.y = packh2(a.z, a.w);
    o.z = packh2(d.x, d.y); o.w = packh2(d.z, d.w);
    *(uint4*)(g_kvinh + e) = o;
}

// ---------------- batched transpose+convert: W[R][C] -> out[C][R] half ----
__global__ void thalf3_kernel(const float* __restrict__ Wq,
                              const float* __restrict__ Wkv,
                              const float* __restrict__ Wout) {
    int z = blockIdx.z;
    const float* in = (z == 0) ? Wq : (z == 1 ? Wkv : Wout);
    __half* out = (z == 0) ? g_wqth : (z == 1 ? g_wkvth : g_wouth);
    int C = (z == 1) ? 2048 : 1024;
    int bx = blockIdx.x << 5, by = blockIdx.y << 5;
    if (bx >= C) return;
    __shared__ float t[32][33];
    int tx = threadIdx.x & 31, ty = threadIdx.x >> 5;
    #pragma unroll
    for (int i = 0; i < 4; i++)
        t[ty + i * 8][tx] = in[(long)(by + ty + i * 8) * C + bx + tx];
    __syncthreads();
    #pragma unroll
    for (int i = 0; i < 4; i++)
        out[(long)(bx + ty + i * 8) * 1024 + by + tx] = __float2half_rn(t[tx][ty + i * 8]);
}

// ---------------- conv weight gather (coalesced float4 reads) -------------
// out[o][k = r*1024 + i] = w[o][i*4 + r]; one thread: one (o,i), 4 outputs.
__global__ void wtt_kernel(const float* __restrict__ w) {
    long idx = (long)blockIdx.x * blockDim.x + threadIdx.x;
    if (idx >= 1048576L) return;
    int o = (int)(idx >> 10), i = (int)(idx & 1023);
    float4 v = *(const float4*)(w + ((long)o << 12) + (i << 2));
    __half* dst = g_wtth + ((long)o << 12) + i;
    dst[0]    = __float2half_rn(v.x);
    dst[1024] = __float2half_rn(v.y);
    dst[2048] = __float2half_rn(v.z);
    dst[3072] = __float2half_rn(v.w);
}

// ---------------- f16 MMA GEMM: C = alpha*A @ Bt^T (+bias) ---------------
// ldmatrix.x4 fragment loads; row stride 56 halves = 112 B, conflict-free.
template<int OUTH>
__global__ __launch_bounds__(256) void hgemm(
    const __half* __restrict__ A, const __half* __restrict__ Bt,
    const float* __restrict__ bias, void* __restrict__ Cv,
    int K, int lda, int ldb, int ldc, float alpha, long sA, long sC)
{
    extern __shared__ __half hsm[];
    __half (*As)[56] = (__half(*)[56])hsm;                 // [2*128][56]
    __half (*Bs)[56] = (__half(*)[56])(hsm + 2 * 128 * 56);

    int z = blockIdx.z;
    A += (long)z * sA;
    int m0 = blockIdx.y << 7, n0 = blockIdx.x << 7;

    int tid = threadIdx.x, warp = tid >> 5, lane = tid & 31;
    int gid = lane >> 2, tg = lane & 3;
    int wm = warp >> 2, wn = warp & 3;   // WM=64, WN=32

    float acc[4][4][4] = {};

    auto issueT = [&](int k0, int buf) {
        #pragma unroll
        for (int i = 0; i < 2; i++) {
            int f = tid + i * 256;
            int r = f >> 2, c = (f & 3) << 3;
            cp16(&As[buf * 128 + r][c], A + (long)(m0 + r) * lda + k0 + c);
            cp16(&Bs[buf * 128 + r][c], Bt + (long)(n0 + r) * ldb + k0 + c);
        }
        cp_commit();
    };

    // ldmatrix bases:
    // A-frag order a0..a3 = (m0-7,k0-7),(m8-15,k0-7),(m0-7,k8-15),(m8-15,k8-15)
    //   lanes 0-15 -> rows 0-15 col 0; lanes 16-31 -> rows 0-15 col +16B
    // B-frag order r0..r3 = (n0-7,k0-7),(n0-7,k8-15),(n8-15,k0-7),(n8-15,k8-15)
    //   lanes 0-7 rows0-7 col0; 8-15 rows0-7 col+16B; 16-23 rows8-15 col0; 24-31 rows8-15 col+16B
    unsigned abase = (unsigned)__cvta_generic_to_shared(&As[0][0])
                   + (lane & 15) * 112u + (lane >> 4) * 16u + (unsigned)(wm * 64) * 112u;
    unsigned bbase = (unsigned)__cvta_generic_to_shared(&Bs[0][0])
                   + ((lane & 7) + ((lane >> 4) << 3)) * 112u + ((lane >> 3) & 1) * 16u
                   + (unsigned)(wn * 32) * 112u;

    issueT(0, 0);
    int nk = K >> 5;
    for (int kt = 0; kt < nk; kt++) {
        int buf = kt & 1;
        if (kt + 1 < nk) {
            __syncthreads();
            issueT((kt + 1) << 5, buf ^ 1);
            cp_wait<1>();
        } else {
            cp_wait<0>();
        }
        __syncthreads();
        unsigned bufOff = (unsigned)buf * 128u * 112u;
        #pragma unroll
        for (int ks = 0; ks < 2; ks++) {
            unsigned af[4][4], b0[4], b1[4];
            #pragma unroll
            for (int mi = 0; mi < 4; mi++)
                ldsm4(af[mi][0], af[mi][1], af[mi][2], af[mi][3],
                      abase + bufOff + (unsigned)(mi * 16) * 112u + ks * 32u);
            ldsm4(b0[0], b0[1], b0[2], b0[3], bbase + bufOff + ks * 32u);
            ldsm4(b1[0], b1[1], b1[2], b1[3], bbase + bufOff + 16u * 112u + ks * 32u);
            #pragma unroll
            for (int mi = 0; mi < 4; mi++) {
                mma_f16(acc[mi][0], af[mi], b0[0], b0[1]);
                mma_f16(acc[mi][1], af[mi], b0[2], b0[3]);
                mma_f16(acc[mi][2], af[mi], b1[0], b1[1]);
                mma_f16(acc[mi][3], af[mi], b1[2], b1[3]);
            }
        }
    }

    #pragma unroll
    for (int mi = 0; mi < 4; mi++) {
        #pragma unroll
        for (int ni = 0; ni < 4; ni++) {
            int r0 = m0 + wm * 64 + mi * 16 + gid;
            int c  = n0 + wn * 32 + ni * 8 + 2 * tg;
            if (OUTH) {
                __half* C = (__half*)Cv + (long)z * sC;
                *(unsigned*)(C + (long)r0 * ldc + c) =
                    packh2(alpha * acc[mi][ni][0], alpha * acc[mi][ni][1]);
                *(unsigned*)(C + (long)(r0 + 8) * ldc + c) =
                    packh2(alpha * acc[mi][ni][2], alpha * acc[mi][ni][3]);
            } else {
                float* C = (float*)Cv + (long)z * sC;
                float b0f = 0.f, b1f = 0.f;
                if (bias) { b0f = bias[c]; b1f = bias[c + 1]; }
                *(float2*)(C + (long)r0 * ldc + c) =
                    make_float2(acc[mi][ni][0] + b0f, acc[mi][ni][1] + b1f);
                *(float2*)(C + (long)(r0 + 8) * ldc + c) =
                    make_float2(acc[mi][ni][2] + b0f, acc[mi][ni][3] + b1f);
            }
        }
    }
}

// ---------------- fused flash attention, fp16, pos ring buffer ------------
// 8 warps, i-tile 128, j-tile 64, grid (1,8,32), 2 CTAs/SM.
// smem (96256 B): Ks[2][64][72]h @0 | Vs[2][64][72]h @18432
//                 Ps[256][72]h ring @36864 | PgH[128][88]h @73728
#define KS_OFF 0
#define VS_OFF 18432
#define PS_OFF 36864
#define PG_OFF 73728
#define FL_SMEM 96256

__global__ __launch_bounds__(256, 2) void flash_kernel() {
    extern __shared__ __align__(16) unsigned char sm[];
    __half (*Ks)[64][72] = (__half(*)[64][72])(sm + KS_OFF);
    __half (*Vs)[64][72] = (__half(*)[64][72])(sm + VS_OFF);
    __half (*Ps)[72]     = (__half(*)[72])(sm + PS_OFF);      // 256-row ring
    __half (*Pg)[88]     = (__half(*)[88])(sm + PG_OFF);

    int bh = blockIdx.z; int b = bh >> 4, h = bh & 15;
    int i0 = blockIdx.y << 7;
    int tid = threadIdx.x, warp = tid >> 5, lane = tid & 31;
    int gid = lane >> 2, tg = lane & 3;

    // Q fragments (g_qh pre-scaled half)
    unsigned qf[4][4];
    {
        const __half* q0 = g_qh + (long)(b * TT + i0 + (warp << 4) + gid) * DD + h * DHD;
        #pragma unroll
        for (int kb = 0; kb < 4; kb++) {
            qf[kb][0] = *(const unsigned*)(q0 + kb * 16 + 2 * tg);
            qf[kb][1] = *(const unsigned*)(q0 + 8 * DD + kb * 16 + 2 * tg);
            qf[kb][2] = *(const unsigned*)(q0 + kb * 16 + 2 * tg + 8);
            qf[kb][3] = *(const unsigned*)(q0 + 8 * DD + kb * 16 + 2 * tg + 8);
        }
    }

    int r = tid >> 2, q4 = (tid & 3) << 4;
    const __half* kvb = g_kvh + ((long)(b * KVL) + r) * 2048 + h * DHD + q4;
    int ub0 = 896 - i0;                      // pos idx of ring-logical row 0 at j0=0

    // load one pos row (pos_idx uu) into ring slot uu&255
    auto loadP = [&](int uu) {
        int phys = uu & 255;
        if (uu < KVL) {
            const __half* pp = g_ph + ((long)h * KVL + uu) * 64 + q4;
            cp16(&Ps[phys][q4], pp); cp16(&Ps[phys][q4 + 8], pp + 8);
        } else {
            uint4 z = make_uint4(0, 0, 0, 0);
            *(uint4*)&Ps[phys][q4] = z; *(uint4*)&Ps[phys][q4 + 8] = z;
        }
    };

    auto issue = [&](int j0, int buf, bool first) {
        const __half* kp = kvb + (long)j0 * 2048;
        cp16(&Ks[buf][r][q4], kp);            cp16(&Ks[buf][r][q4 + 8], kp + 8);
        cp16(&Vs[buf][r][q4], kp + 1024);     cp16(&Vs[buf][r][q4 + 8], kp + 1032);
        int ub = j0 + ub0;
        if (first) {
            loadP(ub + r); loadP(ub + r + 64); loadP(ub + r + 128);
        } else {
            loadP(ub + r + 128);             // only the 64 new rows
        }
        cp_commit();
    };

    // ldmatrix lane offsets (row stride 144 B)
    unsigned frag_off = (lane & 7) * 144 + ((lane >> 3) & 1) * 16 + (lane >> 4) * 1152;
    unsigned kbase = (unsigned)__cvta_generic_to_shared(&Ks[0][0][0]) + frag_off;
    unsigned psbase = (unsigned)__cvta_generic_to_shared(&Ps[0][0]);
    int lanerow = (lane & 7) + ((lane >> 4) << 3);       // row within 16-row window
    unsigned pcol = ((lane >> 3) & 1) << 4;              // 16-byte col half

    // ldmatrix V addresses (trans)
    int vrow = (lane & 7) + ((lane >> 3) & 1) * 8;
    int vcol = (lane >> 4) * 8;
    unsigned vbase = (unsigned)__cvta_generic_to_shared(&Vs[0][vrow][vcol]);

    float oacc[8][4] = {};
    float m0r = -1e30f, m1r = -1e30f, l0r = 0.f, l1r = 0.f;
    int wb = 112 - (warp << 4);
    int pgr0 = (warp << 4) + gid, pgr1 = pgr0 + 8;
    int prow_base = ub0 + wb + lanerow;      // + j0 + np*16, then &255

    issue(0, 0, true);
    for (int t = 0; t < 48; t++) {
        int buf = t & 1;
        cp_wait<0>();
        __syncthreads();

        // ---- S = QK^T (ldmatrix.x4 B-frags, 2 mmas per load) ----
        float sacc[8][4] = {};
        #pragma unroll
        for (int np = 0; np < 4; np++) {
            #pragma unroll
            for (int kb = 0; kb < 4; kb++) {
                unsigned b0, b1, b2, b3;
                ldsm4(b0, b1, b2, b3, kbase + buf * 9216 + np * 2304 + kb * 32);
                mma_f16(sacc[2 * np],     qf[kb], b0, b1);
                mma_f16(sacc[2 * np + 1], qf[kb], b2, b3);
            }
        }

        // ---- band product from ring: 5 pair-passes ----
        int pr = prow_base + (t << 6);
        #pragma unroll
        for (int np = 0; np < 5; np++) {
            float pacc[2][4] = {};
            unsigned pa = psbase + (unsigned)((pr + np * 16) & 255) * 144 + pcol;
            #pragma unroll
            for (int kb = 0; kb < 4; kb++) {
                unsigned b0, b1, b2, b3;
                ldsm4(b0, b1, b2, b3, pa + kb * 32);
                mma_f16(pacc[0], qf[kb], b0, b1);
                mma_f16(pacc[1], qf[kb], b2, b3);
            }
            int c0 = (2 * np) * 8 + 2 * tg;
            *(unsigned*)&Pg[pgr0][c0]     = packh2(pacc[0][0], pacc[0][1]);
            *(unsigned*)&Pg[pgr1][c0]     = packh2(pacc[0][2], pacc[0][3]);
            *(unsigned*)&Pg[pgr0][c0 + 8] = packh2(pacc[1][0], pacc[1][1]);
            *(unsigned*)&Pg[pgr1][c0 + 8] = packh2(pacc[1][2], pacc[1][3]);
        }
        __syncthreads();                     // Ks/Ps consumed, Pg visible
        if (t < 47) issue((t + 1) << 6, buf ^ 1, false);

        // ---- gather shifted band into S ----
        {
            int s0 = 15 - gid, s1 = 7 - gid;
            #pragma unroll
            for (int nb = 0; nb < 8; nb++) {
                int jl = nb * 8 + 2 * tg;
                sacc[nb][0] += __half2float(Pg[pgr0][jl + s0]);
                sacc[nb][1] += __half2float(Pg[pgr0][jl + 1 + s0]);
                sacc[nb][2] += __half2float(Pg[pgr1][jl + s1]);
                sacc[nb][3] += __half2float(Pg[pgr1][jl + 1 + s1]);
            }
        }

        // ---- online softmax (rows quad-local) ----
        float mx0 = -1e30f, mx1 = -1e30f;
        #pragma unroll
        for (int nb = 0; nb < 8; nb++) {
            mx0 = fmaxf(mx0, fmaxf(sacc[nb][0], sacc[nb][1]));
            mx1 = fmaxf(mx1, fmaxf(sacc[nb][2], sacc[nb][3]));
        }
        #pragma unroll
        for (int o = 1; o <= 2; o <<= 1) {
            mx0 = fmaxf(mx0, __shfl_xor_sync(0xffffffffu, mx0, o));
            mx1 = fmaxf(mx1, __shfl_xor_sync(0xffffffffu, mx1, o));
        }
        float mn0 = fmaxf(m0r, mx0), mn1 = fmaxf(m1r, mx1);
        float f0 = __expf(m0r - mn0), f1 = __expf(m1r - mn1);
        m0r = mn0; m1r = mn1;
        float ps0 = 0.f, ps1 = 0.f;
        #pragma unroll
        for (int nb = 0; nb < 8; nb++) {
            sacc[nb][0] = __expf(sacc[nb][0] - mn0);
            sacc[nb][1] = __expf(sacc[nb][1] - mn0);
            sacc[nb][2] = __expf(sacc[nb][2] - mn1);
            sacc[nb][3] = __expf(sacc[nb][3] - mn1);
            ps0 += sacc[nb][0] + sacc[nb][1];
            ps1 += sacc[nb][2] + sacc[nb][3];
            oacc[nb][0] *= f0; oacc[nb][1] *= f0;
            oacc[nb][2] *= f1; oacc[nb][3] *= f1;
        }
        #pragma unroll
        for (int o = 1; o <= 2; o <<= 1) {
            ps0 += __shfl_xor_sync(0xffffffffu, ps0, o);
            ps1 += __shfl_xor_sync(0xffffffffu, ps1, o);
        }
        l0r = l0r * f0 + ps0;
        l1r = l1r * f1 + ps1;

        // ---- AV: probs -> in-register A-frags; V via ldmatrix.trans ----
        #pragma unroll
        for (int kb = 0; kb < 4; kb++) {
            unsigned af[4];
            af[0] = packh2(sacc[2 * kb][0],     sacc[2 * kb][1]);
            af[1] = packh2(sacc[2 * kb][2],     sacc[2 * kb][3]);
            af[2] = packh2(sacc[2 * kb + 1][0], sacc[2 * kb + 1][1]);
            af[3] = packh2(sacc[2 * kb + 1][2], sacc[2 * kb + 1][3]);
            unsigned va = vbase + buf * 9216 + kb * 2304;
            #pragma unroll
            for (int p = 0; p < 4; p++) {
                unsigned b0, b1, b2, b3;
                ldsm4t(b0, b1, b2, b3, va + p * 32);
                mma_f16(oacc[2 * p],     af, b0, b1);
                mma_f16(oacc[2 * p + 1], af, b2, b3);
            }
        }
    }

    // ---- write ctx = O / l as half ----
    float inv0 = 1.0f / l0r, inv1 = 1.0f / l1r;
    #pragma unroll
    for (int nb = 0; nb < 8; nb++) {
        int c = h * DHD + nb * 8 + 2 * tg;
        long r0 = (long)(b * TT + i0 + (warp << 4) + gid) * DD + c;
        *(unsigned*)(g_ctxh + r0)          = packh2(oacc[nb][0] * inv0, oacc[nb][1] * inv0);
        *(unsigned*)(g_ctxh + r0 + 8 * DD) = packh2(oacc[nb][2] * inv1, oacc[nb][3] * inv1);
    }
}

// ---------------- copies + aux -------------------------------------------
__global__ void copy4_kernel(const float4* __restrict__ src, float4* __restrict__ dst, long n4) {
    long i = (long)blockIdx.x * blockDim.x + threadIdx.x;
    if (i < n4) dst[i] = src[i];
}
__global__ void aux_kernel(float* out) { *out = 0.f; }

// ---------------- launch ---------------------------------------------------
extern "C" void kernel_launch(void* const* d_in, const int* in_sizes, int n_in,
                              void* d_out_, int out_size) {
    const float* x      = (const float*)d_in[0];
    const float* mem    = (const float*)d_in[1];
    const float* cmem   = (const float*)d_in[2];
    const float* pos    = (const float*)d_in[3];
    const float* Wq     = (const float*)d_in[4];
    const float* Wkv    = (const float*)d_in[5];
    const float* Wout   = (const float*)d_in[6];
    const float* b_out  = (const float*)d_in[7];
    const float* conv_w = (const float*)d_in[8];
    const float* conv_b = (const float*)d_in[9];
    float* out = (float*)d_out_;

    __half *p_ph, *p_kvinh, *p_qh, *p_kvh, *p_ctxh;
    __half *p_wqth, *p_wkvth, *p_wouth, *p_wtth;
    cudaGetSymbolAddress((void**)&p_ph,    g_ph);
    cudaGetSymbolAddress((void**)&p_kvinh, g_kvinh);
    cudaGetSymbolAddress((void**)&p_qh,    g_qh);
    cudaGetSymbolAddress((void**)&p_kvh,   g_kvh);
    cudaGetSymbolAddress((void**)&p_ctxh,  g_ctxh);
    cudaGetSymbolAddress((void**)&p_wqth,  g_wqth);
    cudaGetSymbolAddress((void**)&p_wkvth, g_wkvth);
    cudaGetSymbolAddress((void**)&p_wouth, g_wouth);
    cudaGetSymbolAddress((void**)&p_wtth,  g_wtth);

    cudaFuncSetAttribute(flash_kernel, cudaFuncAttributeMaxDynamicSharedMemorySize, FL_SMEM);
    cudaFuncSetAttribute(hgemm<0>, cudaFuncAttributeMaxDynamicSharedMemorySize, 57344);
    cudaFuncSetAttribute(hgemm<1>, cudaFuncAttributeMaxDynamicSharedMemorySize, 57344);

    // pre-convert to half
    concat_h_kernel<<<3072, 256>>>(x, mem, cmem);
    cvt_h_kernel<<<1536, 256>>>((const float4*)pos, p_ph, 393216);
    thalf3_kernel<<<dim3(64, 32, 3), 256>>>(Wq, Wkv, Wout);
    wtt_kernel<<<4096, 256>>>(conv_w);

    // q = SCALE * x @ Wq  (x rows live in g_kvinh at offset 2048 per batch)
    hgemm<1><<<dim3(8, 8, 2), 256, 57344>>>(
        p_kvinh + 2048L * 1024, p_wqth, nullptr, p_qh,
        1024, 1024, 1024, 1024, SCALE_F, 3072L * 1024, 1024L * 1024);
    // kv = kv_in @ Wkv  (half out)
    hgemm<1><<<dim3(16, 48, 1), 256, 57344>>>(
        p_kvinh, p_wkvth, nullptr, p_kvh, 1024, 1024, 1024, 2048, 1.0f, 0, 0);

    // fused attention
    flash_kernel<<<dim3(1, 8, 32), 256, FL_SMEM>>>();

    // logits = ctx @ Wout + b_out (f32)
    hgemm<0><<<dim3(8, 16, 1), 256, 57344>>>(
        p_ctxh, p_wouth, b_out, out, 1024, 1024, 1024, 1024, 1.0f, 0, 0);

    // new_mem = x (f32 copy)
    copy4_kernel<<<2048, 256>>>((const float4*)x, (float4*)(out + 2097152), 524288);

    // new_cmem part 1: cmem[:, 256:]
    copy4_kernel<<<768, 256>>>((const float4*)(cmem + 262144),  (float4*)(out + 4194304), 196608);
    copy4_kernel<<<768, 256>>>((const float4*)(cmem + 1310720), (float4*)(out + 5242880), 196608);

    // new_cmem part 2: conv as GEMM (mem rows live in g_kvinh at offset 1024)
    hgemm<0><<<dim3(8, 2, 2), 256, 57344>>>(
        p_kvinh + 1024L * 1024, p_wtth, conv_b, out + 4980736,
        4096, 4096, 4096, 1024, 1.0f, 3072L * 1024, 1048576L);

    // aux_loss = 0
    aux_kernel<<<1, 1>>>(out + 6291456);
}